// round 1
// baseline (speedup 1.0000x reference)
#include <cuda_runtime.h>
#include <math.h>

// Problem dims
#define Bc 2
#define Tc 2048
#define Dc 1024
#define Hc 16
#define Kc 64
#define Vc 64
#define Wc 256
#define MROWS (Bc * Tc)          // 4096
#define CUE_C 50250
#define BANK_C 64

// ---------------- scratch (device globals; no allocs allowed) ----------------
__device__ float g_xn[MROWS * Dc];
__device__ float g_q[MROWS * Dc];
__device__ float g_k[MROWS * Dc];
__device__ float g_v[MROWS * Dc];
__device__ float g_qg[MROWS * Dc];
__device__ float g_local[MROWS * Dc];
__device__ float g_localO[MROWS * Dc];
__device__ float g_ret[MROWS * Dc];
__device__ float g_ro[MROWS * Dc];
__device__ float g_gate[MROWS];

// ---------------- RMSNorm ----------------
__global__ __launch_bounds__(256) void rmsnorm_k(const float* __restrict__ x,
                                                 const float* __restrict__ w) {
    int row = blockIdx.x;
    int tid = threadIdx.x;
    const float4* xr = (const float4*)(x + row * Dc);
    float4 vv = xr[tid];                       // 256 * 4 = 1024
    float s = vv.x * vv.x + vv.y * vv.y + vv.z * vv.z + vv.w * vv.w;
    __shared__ float red[256];
    red[tid] = s;
    __syncthreads();
    for (int o = 128; o > 0; o >>= 1) {
        if (tid < o) red[tid] += red[tid + o];
        __syncthreads();
    }
    float inv = rsqrtf(red[0] * (1.0f / Dc) + 1e-6f);
    float4 wv = ((const float4*)w)[tid];
    float4 o;
    o.x = vv.x * inv * wv.x;
    o.y = vv.y * inv * wv.y;
    o.z = vv.z * inv * wv.z;
    o.w = vv.w * inv * wv.w;
    ((float4*)(g_xn + row * Dc))[tid] = o;
}

// ---------------- SGEMM: C[m][n] = alpha * sum_k A[m][k] * W[n][k] ----------
// 128x128 block tile, BK=8, 256 threads, 8x8 microtile, register prefetch.
__global__ __launch_bounds__(256) void sgemm128(const float* __restrict__ A,
                                                const float* __restrict__ Wt,
                                                float* __restrict__ C,
                                                int Kdim, int N, float alpha) {
    __shared__ float As[8][128];
    __shared__ float Bs[8][128];
    int tid = threadIdx.x;
    int tx = tid & 15;       // 0..15 -> n
    int ty = tid >> 4;       // 0..15 -> m
    int m0 = blockIdx.y * 128;
    int n0 = blockIdx.x * 128;

    int lr = tid >> 1;               // 0..127 row within tile
    int lc = (tid & 1) * 4;          // 0 or 4 k-offset
    const float* Ab = A + (size_t)(m0 + lr) * Kdim + lc;
    const float* Bb = Wt + (size_t)(n0 + lr) * Kdim + lc;

    float4 pa = *(const float4*)Ab;
    float4 pb = *(const float4*)Bb;

    float acc[8][8];
#pragma unroll
    for (int i = 0; i < 8; i++)
#pragma unroll
        for (int j = 0; j < 8; j++) acc[i][j] = 0.f;

    for (int k0 = 0; k0 < Kdim; k0 += 8) {
        As[lc + 0][lr] = pa.x; As[lc + 1][lr] = pa.y;
        As[lc + 2][lr] = pa.z; As[lc + 3][lr] = pa.w;
        Bs[lc + 0][lr] = pb.x; Bs[lc + 1][lr] = pb.y;
        Bs[lc + 2][lr] = pb.z; Bs[lc + 3][lr] = pb.w;
        __syncthreads();
        if (k0 + 8 < Kdim) {
            pa = *(const float4*)(Ab + k0 + 8);
            pb = *(const float4*)(Bb + k0 + 8);
        }
#pragma unroll
        for (int kk = 0; kk < 8; kk++) {
            float af[8], bf[8];
#pragma unroll
            for (int i = 0; i < 8; i++) af[i] = As[kk][ty * 8 + i];
#pragma unroll
            for (int j = 0; j < 8; j++) bf[j] = Bs[kk][tx * 8 + j];
#pragma unroll
            for (int i = 0; i < 8; i++)
#pragma unroll
                for (int j = 0; j < 8; j++) acc[i][j] += af[i] * bf[j];
        }
        __syncthreads();
    }
#pragma unroll
    for (int i = 0; i < 8; i++) {
        float* cr = C + (size_t)(m0 + ty * 8 + i) * N + n0 + tx * 8;
        float4 o0, o1;
        o0.x = alpha * acc[i][0]; o0.y = alpha * acc[i][1];
        o0.z = alpha * acc[i][2]; o0.w = alpha * acc[i][3];
        o1.x = alpha * acc[i][4]; o1.y = alpha * acc[i][5];
        o1.z = alpha * acc[i][6]; o1.w = alpha * acc[i][7];
        ((float4*)cr)[0] = o0;
        ((float4*)cr)[1] = o1;
    }
}

// ---------------- gate: mean_h sigmoid(x_norm . w_gate[h] + b[h]) -----------
__global__ __launch_bounds__(512) void gate_k(const float* __restrict__ wg,
                                              const float* __restrict__ bg) {
    int row = blockIdx.x;
    int w = threadIdx.x >> 5;
    int lane = threadIdx.x & 31;
    const float* xr = g_xn + row * Dc;
    const float* wr = wg + w * Dc;
    float s = 0.f;
    for (int d = lane; d < Dc; d += 32) s += xr[d] * wr[d];
#pragma unroll
    for (int o = 16; o > 0; o >>= 1) s += __shfl_xor_sync(0xffffffffu, s, o);
    __shared__ float hs[16];
    if (lane == 0) hs[w] = 1.f / (1.f + __expf(-(s + bg[w])));
    __syncthreads();
    if (threadIdx.x == 0) {
        float m = 0.f;
#pragma unroll
        for (int h = 0; h < 16; h++) m += hs[h];
        g_gate[row] = m * (1.f / 16.f);
    }
}

// ---------------- RoPE (in place) ----------------
__global__ __launch_bounds__(256) void rope_k(float* __restrict__ p) {
    int gid = blockIdx.x * 256 + threadIdx.x;  // MROWS*H*32 = 2097152 total
    int row = gid >> 9;
    int rem = gid & 511;
    int h = rem >> 5;
    int i = rem & 31;
    int t = row & (Tc - 1);
    int base = row * Dc + h * 64 + i;
    float u1 = p[base];
    float u2 = p[base + 32];
    // inv_freq = 10000^(-(2i)/64) = exp2(-i * log2(10000)/32)
    float fr = exp2f(-(float)i * 0.41524100184f);
    float ang = (float)t * fr;
    float c, s;
    __sincosf(ang, &s, &c);
    p[base] = u1 * c - u2 * s;
    p[base + 32] = u2 * c + u1 * s;
}

// ---------------- sliding-window attention ----------------
// One block = (b, h, 128 queries). Online softmax over key tiles of 64.
#define ATTN_SMEM ((64 * 68 * 2 + 128 * 65) * 4)
__global__ __launch_bounds__(128) void attn_k() {
    extern __shared__ float sm[];
    float* ks = sm;               // 64 x 68
    float* vs = sm + 64 * 68;     // 64 x 68
    float* ps = sm + 2 * 64 * 68; // 128 x 65 (q staging, then scores)
    int tid = threadIdx.x;
    int q0 = blockIdx.x * 128;
    int h = blockIdx.y;
    int b = blockIdx.z;
    int tq = q0 + tid;

    // stage q tile coalesced, then copy own row to registers
    const float* qbase = g_q + (size_t)(b * Tc + q0) * Dc + h * 64;
#pragma unroll 4
    for (int it = 0; it < 64; it++) {
        int id = it * 128 + tid;
        int r = id >> 6, d = id & 63;
        ps[r * 65 + d] = qbase[(size_t)r * Dc + d];
    }
    __syncthreads();
    float qv[64];
#pragma unroll
    for (int d = 0; d < 64; d++) qv[d] = ps[tid * 65 + d];
    __syncthreads();

    float m = -1e30f, l = 0.f;
    float acc[64];
#pragma unroll
    for (int d = 0; d < 64; d++) acc[d] = 0.f;

    int s_start = q0 - Wc;
    if (s_start < 0) s_start = 0;
    for (int s0 = s_start; s0 < q0 + 128; s0 += 64) {
        const float* kb = g_k + (size_t)(b * Tc + s0) * Dc + h * 64;
        const float* vb = g_v + (size_t)(b * Tc + s0) * Dc + h * 64;
#pragma unroll 4
        for (int it = 0; it < 32; it++) {
            int id = it * 128 + tid;
            int r = id >> 6, d = id & 63;
            ks[r * 68 + d] = kb[(size_t)r * Dc + d];
            vs[r * 68 + d] = vb[(size_t)r * Dc + d];
        }
        __syncthreads();

        float tmax = -1e30f;
        for (int j = 0; j < 64; j++) {
            const float4* k4 = (const float4*)(ks + j * 68);
            float s = 0.f;
#pragma unroll
            for (int d4 = 0; d4 < 16; d4++) {
                float4 kvv = k4[d4];
                s += qv[d4 * 4 + 0] * kvv.x;
                s += qv[d4 * 4 + 1] * kvv.y;
                s += qv[d4 * 4 + 2] * kvv.z;
                s += qv[d4 * 4 + 3] * kvv.w;
            }
            s *= 0.125f;  // K^-0.5
            int sg = s0 + j;
            if (sg > tq || sg < tq - Wc) s = -1e30f;
            ps[tid * 65 + j] = s;
            tmax = fmaxf(tmax, s);
        }
        float mnew = fmaxf(m, tmax);
        float corr = __expf(m - mnew);
        l *= corr;
#pragma unroll
        for (int d = 0; d < 64; d++) acc[d] *= corr;
        for (int j = 0; j < 64; j++) {
            float sv = ps[tid * 65 + j];
            float p = (sv > -1e29f) ? __expf(sv - mnew) : 0.f;
            l += p;
            const float4* v4 = (const float4*)(vs + j * 68);
#pragma unroll
            for (int d4 = 0; d4 < 16; d4++) {
                float4 vvv = v4[d4];
                acc[d4 * 4 + 0] += p * vvv.x;
                acc[d4 * 4 + 1] += p * vvv.y;
                acc[d4 * 4 + 2] += p * vvv.z;
                acc[d4 * 4 + 3] += p * vvv.w;
            }
        }
        m = mnew;
        __syncthreads();
    }
    float inv = 1.f / l;
    float* ob = g_local + (size_t)(b * Tc + tq) * Dc + h * 64;
#pragma unroll
    for (int d = 0; d < 64; d++) ob[d] = acc[d] * inv;
}

// ---------------- retrieval: gather-override q_g, apply gdn_state -----------
__global__ __launch_bounds__(256) void retr_k(const float* __restrict__ state,
                                              const int* __restrict__ ids,
                                              const float* __restrict__ bank) {
    __shared__ float st[64 * 64];
    __shared__ float qs[4][64];
    int tc = blockIdx.x;  // 16 chunks of 128 t
    int h = blockIdx.y;
    int b = blockIdx.z;
    int tid = threadIdx.x;
    const float* sb = state + (size_t)((b * Hc + h) * 64) * 64;
    for (int i = tid; i < 4096; i += 256) st[i] = sb[i];
    __syncthreads();
    int tloc = tid >> 6;
    int kk = tid & 63;
    for (int t0 = tc * 128; t0 < tc * 128 + 128; t0 += 4) {
        int t = t0 + tloc;
        int ii = ids[b * Tc + t] - CUE_C;
        float val;
        if (ii >= 0 && ii < BANK_C)
            val = bank[(size_t)(h * BANK_C + ii) * 64 + kk];
        else
            val = g_qg[(size_t)(b * Tc + t) * Dc + h * 64 + kk];
        qs[tloc][kk] = val;
        __syncthreads();
        float sum = 0.f;
#pragma unroll
        for (int k2 = 0; k2 < 64; k2++) sum += st[k2 * 64 + kk] * qs[tloc][k2];
        g_ret[(size_t)(b * Tc + t) * Dc + h * 64 + kk] = sum;
        __syncthreads();
    }
}

// ---------------- final combine ----------------
__global__ __launch_bounds__(256) void combine_k(const float* __restrict__ x,
                                                 float* __restrict__ out) {
    int idx = blockIdx.x * 256 + threadIdx.x;  // 1048576 float4
    int row = idx >> 8;                        // 256 float4 per row
    float g = g_gate[row];
    float4 xv = ((const float4*)x)[idx];
    float4 lv = ((const float4*)g_localO)[idx];
    float4 rv = ((const float4*)g_ro)[idx];
    float4 o;
    o.x = xv.x + lv.x + g * rv.x;
    o.y = xv.y + lv.y + g * rv.y;
    o.z = xv.z + lv.z + g * rv.z;
    o.w = xv.w + lv.w + g * rv.w;
    ((float4*)out)[idx] = o;
}

// ---------------- launch ----------------
extern "C" void kernel_launch(void* const* d_in, const int* in_sizes, int n_in,
                              void* d_out, int out_size) {
    const float* x = (const float*)d_in[0];
    const float* gdn = (const float*)d_in[1];
    const int* ids = (const int*)d_in[2];
    const float* bank = (const float*)d_in[3];
    const float* normw = (const float*)d_in[4];
    const float* wq = (const float*)d_in[5];
    const float* wk = (const float*)d_in[6];
    const float* wv = (const float*)d_in[7];
    const float* wo = (const float*)d_in[8];
    const float* wgq = (const float*)d_in[9];
    const float* wro = (const float*)d_in[10];
    const float* wgate = (const float*)d_in[11];
    const float* bgate = (const float*)d_in[12];
    float* out = (float*)d_out;

    float *xn, *q, *k, *v, *qg, *loc, *locO, *ret, *ro;
    cudaGetSymbolAddress((void**)&xn, g_xn);
    cudaGetSymbolAddress((void**)&q, g_q);
    cudaGetSymbolAddress((void**)&k, g_k);
    cudaGetSymbolAddress((void**)&v, g_v);
    cudaGetSymbolAddress((void**)&qg, g_qg);
    cudaGetSymbolAddress((void**)&loc, g_local);
    cudaGetSymbolAddress((void**)&locO, g_localO);
    cudaGetSymbolAddress((void**)&ret, g_ret);
    cudaGetSymbolAddress((void**)&ro, g_ro);

    cudaFuncSetAttribute(attn_k, cudaFuncAttributeMaxDynamicSharedMemorySize,
                         ATTN_SMEM);

    rmsnorm_k<<<MROWS, 256>>>(x, normw);

    dim3 gg(Dc / 128, MROWS / 128);  // (8, 32)
    sgemm128<<<gg, 256>>>(xn, wq, q, Dc, Dc, 1.0f);
    sgemm128<<<gg, 256>>>(xn, wk, k, Dc, Dc, 1.0f);
    sgemm128<<<gg, 256>>>(xn, wv, v, Dc, Dc, 1.0f);
    sgemm128<<<gg, 256>>>(xn, wgq, qg, Dc, Dc, 1.0f);

    gate_k<<<MROWS, 512>>>(wgate, bgate);

    rope_k<<<(MROWS * Hc * 32) / 256, 256>>>(q);
    rope_k<<<(MROWS * Hc * 32) / 256, 256>>>(k);

    attn_k<<<dim3(Tc / 128, Hc, Bc), 128, ATTN_SMEM>>>();

    sgemm128<<<gg, 256>>>(loc, wo, locO, Dc, Dc, 0.3f);  // LOCAL_SCALE folded

    retr_k<<<dim3(Tc / 128, Hc, Bc), 256>>>(gdn, ids, bank);

    sgemm128<<<gg, 256>>>(ret, wro, ro, Dc, Dc, 1.0f);

    combine_k<<<(MROWS * Dc / 4) / 256, 256>>>(x, out);
}

// round 4
// speedup vs baseline: 1.8332x; 1.8332x over previous
#include <cuda_runtime.h>
#include <math.h>
#include <stdint.h>

// Problem dims
#define Bc 2
#define Tc 2048
#define Dc 1024
#define Hc 16
#define Kc 64
#define Vc 64
#define Wc 256
#define MROWS (Bc * Tc)          // 4096
#define CUE_C 50250
#define BANK_C 64

// ---------------- scratch (device globals; no allocs allowed) ----------------
__device__ float g_xn[MROWS * Dc];
__device__ float g_q[MROWS * Dc];
__device__ float g_k[MROWS * Dc];
__device__ float g_v[MROWS * Dc];
__device__ float g_qg[MROWS * Dc];
__device__ float g_local[MROWS * Dc];
__device__ float g_localO[MROWS * Dc];
__device__ float g_ret[MROWS * Dc];
__device__ float g_ro[MROWS * Dc];
__device__ float g_gate[MROWS];

// ---------------- helpers ----------------
__device__ __forceinline__ uint32_t f2tf(float f) {
    uint32_t r;
    asm("cvt.rna.tf32.f32 %0, %1;" : "=r"(r) : "f"(f));
    return r;
}

__device__ __forceinline__ void mma_tf32(float& d0, float& d1, float& d2, float& d3,
                                         uint32_t a0, uint32_t a1, uint32_t a2, uint32_t a3,
                                         uint32_t b0, uint32_t b1) {
    asm volatile(
        "mma.sync.aligned.m16n8k8.row.col.f32.tf32.tf32.f32 "
        "{%0,%1,%2,%3}, {%4,%5,%6,%7}, {%8,%9}, {%0,%1,%2,%3};\n"
        : "+f"(d0), "+f"(d1), "+f"(d2), "+f"(d3)
        : "r"(a0), "r"(a1), "r"(a2), "r"(a3), "r"(b0), "r"(b1));
}

// ---------------- RMSNorm ----------------
__global__ __launch_bounds__(256) void rmsnorm_k(const float* __restrict__ x,
                                                 const float* __restrict__ w) {
    int row = blockIdx.x;
    int tid = threadIdx.x;
    const float4* xr = (const float4*)(x + row * Dc);
    float4 vv = xr[tid];
    float s = vv.x * vv.x + vv.y * vv.y + vv.z * vv.z + vv.w * vv.w;
    __shared__ float red[256];
    red[tid] = s;
    __syncthreads();
    for (int o = 128; o > 0; o >>= 1) {
        if (tid < o) red[tid] += red[tid + o];
        __syncthreads();
    }
    float inv = rsqrtf(red[0] * (1.0f / Dc) + 1e-6f);
    float4 wv = ((const float4*)w)[tid];
    float4 o;
    o.x = vv.x * inv * wv.x;
    o.y = vv.y * inv * wv.y;
    o.z = vv.z * inv * wv.z;
    o.w = vv.w * inv * wv.w;
    ((float4*)(g_xn + row * Dc))[tid] = o;
}

// ---------------- tf32 tensor-core GEMM ----------------
// C[m][n] = alpha * sum_k A[m][k] * W[n][k];  M=4096, N=K=1024.
// 128x128 block, BK=16, 256 thr (8 warps, 2x4), warp tile 64x32 (4x4 m16n8k8).
#define PADW 20
__global__ __launch_bounds__(256) void tgemm(const float* __restrict__ A,
                                             const float* __restrict__ Wt,
                                             float* __restrict__ C,
                                             float alpha) {
    __shared__ uint32_t As[128 * PADW];
    __shared__ uint32_t Bs[128 * PADW];
    int tid = threadIdx.x;
    int lane = tid & 31;
    int wid = tid >> 5;
    int wm = (wid >> 2) * 64;
    int wn = (wid & 3) * 32;
    int r = lane >> 2;
    int c = lane & 3;
    int m0 = blockIdx.y * 128;
    int n0 = blockIdx.x * 128;

    // global load mapping: 512 float4 per tile per matrix, 2 per thread
    int row0 = tid >> 2;        // 0..63
    int kq = (tid & 3) * 4;     // float4 column offset
    const float* Ab0 = A + (size_t)(m0 + row0) * Dc + kq;
    const float* Ab1 = A + (size_t)(m0 + row0 + 64) * Dc + kq;
    const float* Bb0 = Wt + (size_t)(n0 + row0) * Dc + kq;
    const float* Bb1 = Wt + (size_t)(n0 + row0 + 64) * Dc + kq;

    float4 pa0 = *(const float4*)Ab0;
    float4 pa1 = *(const float4*)Ab1;
    float4 pb0 = *(const float4*)Bb0;
    float4 pb1 = *(const float4*)Bb1;

    float acc[4][4][4];
#pragma unroll
    for (int i = 0; i < 4; i++)
#pragma unroll
        for (int j = 0; j < 4; j++)
#pragma unroll
            for (int e = 0; e < 4; e++) acc[i][j][e] = 0.f;

    const int nIter = Dc / 16;  // 64
    for (int it = 0; it < nIter; it++) {
        // convert + store to smem
        uint32_t* as0 = As + row0 * PADW + kq;
        as0[0] = f2tf(pa0.x); as0[1] = f2tf(pa0.y);
        as0[2] = f2tf(pa0.z); as0[3] = f2tf(pa0.w);
        uint32_t* as1 = As + (row0 + 64) * PADW + kq;
        as1[0] = f2tf(pa1.x); as1[1] = f2tf(pa1.y);
        as1[2] = f2tf(pa1.z); as1[3] = f2tf(pa1.w);
        uint32_t* bs0 = Bs + row0 * PADW + kq;
        bs0[0] = f2tf(pb0.x); bs0[1] = f2tf(pb0.y);
        bs0[2] = f2tf(pb0.z); bs0[3] = f2tf(pb0.w);
        uint32_t* bs1 = Bs + (row0 + 64) * PADW + kq;
        bs1[0] = f2tf(pb1.x); bs1[1] = f2tf(pb1.y);
        bs1[2] = f2tf(pb1.z); bs1[3] = f2tf(pb1.w);
        __syncthreads();

        if (it + 1 < nIter) {
            int off = (it + 1) * 16;
            pa0 = *(const float4*)(Ab0 + off);
            pa1 = *(const float4*)(Ab1 + off);
            pb0 = *(const float4*)(Bb0 + off);
            pb1 = *(const float4*)(Bb1 + off);
        }

#pragma unroll
        for (int ks = 0; ks < 16; ks += 8) {
            uint32_t af[4][4], bf[4][2];
#pragma unroll
            for (int mt = 0; mt < 4; mt++) {
                const uint32_t* p = As + (wm + mt * 16 + r) * PADW + ks + c;
                af[mt][0] = p[0];
                af[mt][1] = p[8 * PADW];
                af[mt][2] = p[4];
                af[mt][3] = p[8 * PADW + 4];
            }
#pragma unroll
            for (int nt = 0; nt < 4; nt++) {
                const uint32_t* p = Bs + (wn + nt * 8 + r) * PADW + ks + c;
                bf[nt][0] = p[0];
                bf[nt][1] = p[4];
            }
#pragma unroll
            for (int mt = 0; mt < 4; mt++)
#pragma unroll
                for (int nt = 0; nt < 4; nt++)
                    mma_tf32(acc[mt][nt][0], acc[mt][nt][1], acc[mt][nt][2], acc[mt][nt][3],
                             af[mt][0], af[mt][1], af[mt][2], af[mt][3],
                             bf[nt][0], bf[nt][1]);
        }
        __syncthreads();
    }

    // epilogue
#pragma unroll
    for (int mt = 0; mt < 4; mt++) {
#pragma unroll
        for (int nt = 0; nt < 4; nt++) {
            float* p = C + (size_t)(m0 + wm + mt * 16 + r) * Dc + n0 + wn + nt * 8 + 2 * c;
            float2 v0, v1;
            v0.x = alpha * acc[mt][nt][0];
            v0.y = alpha * acc[mt][nt][1];
            v1.x = alpha * acc[mt][nt][2];
            v1.y = alpha * acc[mt][nt][3];
            *(float2*)p = v0;
            *(float2*)(p + 8 * Dc) = v1;
        }
    }
}

// ---------------- gate ----------------
__global__ __launch_bounds__(512) void gate_k(const float* __restrict__ wg,
                                              const float* __restrict__ bg) {
    int row = blockIdx.x;
    int w = threadIdx.x >> 5;
    int lane = threadIdx.x & 31;
    const float* xr = g_xn + row * Dc;
    const float* wr = wg + w * Dc;
    float s = 0.f;
    for (int d = lane; d < Dc; d += 32) s += xr[d] * wr[d];
#pragma unroll
    for (int o = 16; o > 0; o >>= 1) s += __shfl_xor_sync(0xffffffffu, s, o);
    __shared__ float hs[16];
    if (lane == 0) hs[w] = 1.f / (1.f + __expf(-(s + bg[w])));
    __syncthreads();
    if (threadIdx.x == 0) {
        float m = 0.f;
#pragma unroll
        for (int h = 0; h < 16; h++) m += hs[h];
        g_gate[row] = m * (1.f / 16.f);
    }
}

// ---------------- RoPE (in place) ----------------
__global__ __launch_bounds__(256) void rope_k(float* __restrict__ p) {
    int gid = blockIdx.x * 256 + threadIdx.x;
    int row = gid >> 9;
    int rem = gid & 511;
    int h = rem >> 5;
    int i = rem & 31;
    int t = row & (Tc - 1);
    int base = row * Dc + h * 64 + i;
    float u1 = p[base];
    float u2 = p[base + 32];
    float fr = exp2f(-(float)i * 0.41524100184f);
    float ang = (float)t * fr;
    float cc, ss;
    __sincosf(ang, &ss, &cc);
    p[base] = u1 * cc - u2 * ss;
    p[base + 32] = u2 * cc + u1 * ss;
}

// ---------------- sliding-window attention ----------------
#define ATTN_SMEM ((64 * 68 * 2 + 128 * 65) * 4)
__global__ __launch_bounds__(128) void attn_k() {
    extern __shared__ float sm[];
    float* ks = sm;
    float* vs = sm + 64 * 68;
    float* ps = sm + 2 * 64 * 68;
    int tid = threadIdx.x;
    int q0 = blockIdx.x * 128;
    int h = blockIdx.y;
    int b = blockIdx.z;
    int tq = q0 + tid;

    const float* qbase = g_q + (size_t)(b * Tc + q0) * Dc + h * 64;
#pragma unroll 4
    for (int it = 0; it < 64; it++) {
        int id = it * 128 + tid;
        int r = id >> 6, d = id & 63;
        ps[r * 65 + d] = qbase[(size_t)r * Dc + d];
    }
    __syncthreads();
    float qv[64];
#pragma unroll
    for (int d = 0; d < 64; d++) qv[d] = ps[tid * 65 + d];
    __syncthreads();

    float m = -1e30f, l = 0.f;
    float acc[64];
#pragma unroll
    for (int d = 0; d < 64; d++) acc[d] = 0.f;

    int s_start = q0 - Wc;
    if (s_start < 0) s_start = 0;
    for (int s0 = s_start; s0 < q0 + 128; s0 += 64) {
        const float* kb = g_k + (size_t)(b * Tc + s0) * Dc + h * 64;
        const float* vb = g_v + (size_t)(b * Tc + s0) * Dc + h * 64;
#pragma unroll 4
        for (int it = 0; it < 32; it++) {
            int id = it * 128 + tid;
            int r = id >> 6, d = id & 63;
            ks[r * 68 + d] = kb[(size_t)r * Dc + d];
            vs[r * 68 + d] = vb[(size_t)r * Dc + d];
        }
        __syncthreads();

        float tmax = -1e30f;
        for (int j = 0; j < 64; j++) {
            const float4* k4 = (const float4*)(ks + j * 68);
            float s = 0.f;
#pragma unroll
            for (int d4 = 0; d4 < 16; d4++) {
                float4 kvv = k4[d4];
                s += qv[d4 * 4 + 0] * kvv.x;
                s += qv[d4 * 4 + 1] * kvv.y;
                s += qv[d4 * 4 + 2] * kvv.z;
                s += qv[d4 * 4 + 3] * kvv.w;
            }
            s *= 0.125f;
            int sg = s0 + j;
            if (sg > tq || sg < tq - Wc) s = -1e30f;
            ps[tid * 65 + j] = s;
            tmax = fmaxf(tmax, s);
        }
        float mnew = fmaxf(m, tmax);
        float corr = __expf(m - mnew);
        l *= corr;
#pragma unroll
        for (int d = 0; d < 64; d++) acc[d] *= corr;
        for (int j = 0; j < 64; j++) {
            float sv = ps[tid * 65 + j];
            float p = (sv > -1e29f) ? __expf(sv - mnew) : 0.f;
            l += p;
            const float4* v4 = (const float4*)(vs + j * 68);
#pragma unroll
            for (int d4 = 0; d4 < 16; d4++) {
                float4 vvv = v4[d4];
                acc[d4 * 4 + 0] += p * vvv.x;
                acc[d4 * 4 + 1] += p * vvv.y;
                acc[d4 * 4 + 2] += p * vvv.z;
                acc[d4 * 4 + 3] += p * vvv.w;
            }
        }
        m = mnew;
        __syncthreads();
    }
    float inv = 1.f / l;
    float* ob = g_local + (size_t)(b * Tc + tq) * Dc + h * 64;
#pragma unroll
    for (int d = 0; d < 64; d++) ob[d] = acc[d] * inv;
}

// ---------------- retrieval ----------------
__global__ __launch_bounds__(256) void retr_k(const float* __restrict__ state,
                                              const int* __restrict__ ids,
                                              const float* __restrict__ bank) {
    __shared__ float st[64 * 64];
    __shared__ float qs[4][64];
    int tc = blockIdx.x;
    int h = blockIdx.y;
    int b = blockIdx.z;
    int tid = threadIdx.x;
    const float* sb = state + (size_t)((b * Hc + h) * 64) * 64;
    for (int i = tid; i < 4096; i += 256) st[i] = sb[i];
    __syncthreads();
    int tloc = tid >> 6;
    int kk = tid & 63;
    for (int t0 = tc * 128; t0 < tc * 128 + 128; t0 += 4) {
        int t = t0 + tloc;
        int ii = ids[b * Tc + t] - CUE_C;
        float val;
        if (ii >= 0 && ii < BANK_C)
            val = bank[(size_t)(h * BANK_C + ii) * 64 + kk];
        else
            val = g_qg[(size_t)(b * Tc + t) * Dc + h * 64 + kk];
        qs[tloc][kk] = val;
        __syncthreads();
        float sum = 0.f;
#pragma unroll
        for (int k2 = 0; k2 < 64; k2++) sum += st[k2 * 64 + kk] * qs[tloc][k2];
        g_ret[(size_t)(b * Tc + t) * Dc + h * 64 + kk] = sum;
        __syncthreads();
    }
}

// ---------------- final combine ----------------
__global__ __launch_bounds__(256) void combine_k(const float* __restrict__ x,
                                                 float* __restrict__ out) {
    int idx = blockIdx.x * 256 + threadIdx.x;
    int row = idx >> 8;
    float g = g_gate[row];
    float4 xv = ((const float4*)x)[idx];
    float4 lv = ((const float4*)g_localO)[idx];
    float4 rv = ((const float4*)g_ro)[idx];
    float4 o;
    o.x = xv.x + lv.x + g * rv.x;
    o.y = xv.y + lv.y + g * rv.y;
    o.z = xv.z + lv.z + g * rv.z;
    o.w = xv.w + lv.w + g * rv.w;
    ((float4*)out)[idx] = o;
}

// ---------------- launch ----------------
extern "C" void kernel_launch(void* const* d_in, const int* in_sizes, int n_in,
                              void* d_out, int out_size) {
    const float* x = (const float*)d_in[0];
    const float* gdn = (const float*)d_in[1];
    const int* ids = (const int*)d_in[2];
    const float* bank = (const float*)d_in[3];
    const float* normw = (const float*)d_in[4];
    const float* wq = (const float*)d_in[5];
    const float* wk = (const float*)d_in[6];
    const float* wv = (const float*)d_in[7];
    const float* wo = (const float*)d_in[8];
    const float* wgq = (const float*)d_in[9];
    const float* wro = (const float*)d_in[10];
    const float* wgate = (const float*)d_in[11];
    const float* bgate = (const float*)d_in[12];
    float* out = (float*)d_out;

    float *xn, *q, *k, *v, *qg, *loc, *locO, *ret, *ro;
    cudaGetSymbolAddress((void**)&xn, g_xn);
    cudaGetSymbolAddress((void**)&q, g_q);
    cudaGetSymbolAddress((void**)&k, g_k);
    cudaGetSymbolAddress((void**)&v, g_v);
    cudaGetSymbolAddress((void**)&qg, g_qg);
    cudaGetSymbolAddress((void**)&loc, g_local);
    cudaGetSymbolAddress((void**)&locO, g_localO);
    cudaGetSymbolAddress((void**)&ret, g_ret);
    cudaGetSymbolAddress((void**)&ro, g_ro);

    cudaFuncSetAttribute(attn_k, cudaFuncAttributeMaxDynamicSharedMemorySize,
                         ATTN_SMEM);

    rmsnorm_k<<<MROWS, 256>>>(x, normw);

    dim3 gg(Dc / 128, MROWS / 128);  // (8, 32)
    tgemm<<<gg, 256>>>(xn, wq, q, 1.0f);
    tgemm<<<gg, 256>>>(xn, wk, k, 1.0f);
    tgemm<<<gg, 256>>>(xn, wv, v, 1.0f);
    tgemm<<<gg, 256>>>(xn, wgq, qg, 1.0f);

    gate_k<<<MROWS, 512>>>(wgate, bgate);

    rope_k<<<(MROWS * Hc * 32) / 256, 256>>>(q);
    rope_k<<<(MROWS * Hc * 32) / 256, 256>>>(k);

    attn_k<<<dim3(Tc / 128, Hc, Bc), 128, ATTN_SMEM>>>();

    tgemm<<<gg, 256>>>(loc, wo, locO, 0.3f);

    retr_k<<<dim3(Tc / 128, Hc, Bc), 256>>>(gdn, ids, bank);

    tgemm<<<gg, 256>>>(ret, wro, ro, 1.0f);

    combine_k<<<(MROWS * Dc / 4) / 256, 256>>>(x, out);
}

// round 5
// speedup vs baseline: 2.0969x; 1.1438x over previous
#include <cuda_runtime.h>
#include <math.h>
#include <stdint.h>

// Problem dims
#define Bc 2
#define Tc 2048
#define Dc 1024
#define Hc 16
#define Kc 64
#define Vc 64
#define Wc 256
#define MROWS (Bc * Tc)          // 4096
#define CUE_C 50250
#define BANK_C 64

// ---------------- scratch (device globals; no allocs allowed) ----------------
__device__ float g_xn[MROWS * Dc];
__device__ float g_q[MROWS * Dc];
__device__ float g_k[MROWS * Dc];
__device__ float g_v[MROWS * Dc];
__device__ float g_qg[MROWS * Dc];
__device__ float g_local[MROWS * Dc];
__device__ float g_localO[MROWS * Dc];
__device__ float g_ret[MROWS * Dc];
__device__ float g_ro[MROWS * Dc];
__device__ float g_gate[MROWS];

// ---------------- helpers ----------------
__device__ __forceinline__ uint32_t f2tf(float f) {
    uint32_t r;
    asm("cvt.rna.tf32.f32 %0, %1;" : "=r"(r) : "f"(f));
    return r;
}

__device__ __forceinline__ void mma_tf32(float& d0, float& d1, float& d2, float& d3,
                                         uint32_t a0, uint32_t a1, uint32_t a2, uint32_t a3,
                                         uint32_t b0, uint32_t b1) {
    asm volatile(
        "mma.sync.aligned.m16n8k8.row.col.f32.tf32.tf32.f32 "
        "{%0,%1,%2,%3}, {%4,%5,%6,%7}, {%8,%9}, {%0,%1,%2,%3};\n"
        : "+f"(d0), "+f"(d1), "+f"(d2), "+f"(d3)
        : "r"(a0), "r"(a1), "r"(a2), "r"(a3), "r"(b0), "r"(b1));
}

__device__ __forceinline__ void cpa16(void* smem, const void* gmem) {
    uint32_t s = (uint32_t)__cvta_generic_to_shared(smem);
    asm volatile("cp.async.cg.shared.global [%0], [%1], 16;\n" ::"r"(s), "l"(gmem));
}
#define CP_COMMIT() asm volatile("cp.async.commit_group;\n" ::: "memory")
#define CP_WAIT0() asm volatile("cp.async.wait_group 0;\n" ::: "memory")

// ---------------- RMSNorm ----------------
__global__ __launch_bounds__(256) void rmsnorm_k(const float* __restrict__ x,
                                                 const float* __restrict__ w) {
    int row = blockIdx.x;
    int tid = threadIdx.x;
    const float4* xr = (const float4*)(x + row * Dc);
    float4 vv = xr[tid];
    float s = vv.x * vv.x + vv.y * vv.y + vv.z * vv.z + vv.w * vv.w;
    __shared__ float red[256];
    red[tid] = s;
    __syncthreads();
    for (int o = 128; o > 0; o >>= 1) {
        if (tid < o) red[tid] += red[tid + o];
        __syncthreads();
    }
    float inv = rsqrtf(red[0] * (1.0f / Dc) + 1e-6f);
    float4 wv = ((const float4*)w)[tid];
    float4 o;
    o.x = vv.x * inv * wv.x;
    o.y = vv.y * inv * wv.y;
    o.z = vv.z * inv * wv.z;
    o.w = vv.w * inv * wv.w;
    ((float4*)(g_xn + row * Dc))[tid] = o;
}

// ---------------- tf32 tensor-core GEMM, 2-stage cp.async pipeline ----------
// C[m][n] = alpha * sum_k A[m][k] * W[n][k];  M=4096, N=K=1024.
// 128x128 block, BK=16, 256 thr (8 warps 2x4), warp tile 64x32 (4x4 m16n8k8).
#define PADW 20
#define STG (128 * PADW)

struct GemmPtrs {
    const float* A;
    const float* W;
    float* C;
};

__device__ __forceinline__ void gemm_body(const float* __restrict__ A,
                                          const float* __restrict__ Wt,
                                          float* __restrict__ C, float alpha,
                                          int bx, int by,
                                          float* As, float* Bs) {
    int tid = threadIdx.x;
    int lane = tid & 31;
    int wid = tid >> 5;
    int wm = (wid >> 2) * 64;
    int wn = (wid & 3) * 32;
    int r = lane >> 2;
    int c = lane & 3;
    int m0 = by * 128;
    int n0 = bx * 128;

    int row0 = tid >> 2;        // 0..63
    int kq = (tid & 3) * 4;     // float column offset (16B aligned)
    const float* Ab0 = A + (size_t)(m0 + row0) * Dc + kq;
    const float* Ab1 = A + (size_t)(m0 + row0 + 64) * Dc + kq;
    const float* Bb0 = Wt + (size_t)(n0 + row0) * Dc + kq;
    const float* Bb1 = Wt + (size_t)(n0 + row0 + 64) * Dc + kq;

    float acc[4][4][4];
#pragma unroll
    for (int i = 0; i < 4; i++)
#pragma unroll
        for (int j = 0; j < 4; j++)
#pragma unroll
            for (int e = 0; e < 4; e++) acc[i][j][e] = 0.f;

    const int nIter = Dc / 16;  // 64

    // prologue: stage 0
    {
        float* as = As;  // stage 0
        float* bs = Bs;
        cpa16(as + row0 * PADW + kq, Ab0);
        cpa16(as + (row0 + 64) * PADW + kq, Ab1);
        cpa16(bs + row0 * PADW + kq, Bb0);
        cpa16(bs + (row0 + 64) * PADW + kq, Bb1);
        CP_COMMIT();
    }

    for (int it = 0; it < nIter; it++) {
        CP_WAIT0();
        __syncthreads();

        if (it + 1 < nIter) {
            int off = (it + 1) * 16;
            int st = (it + 1) & 1;
            float* as = As + st * STG;
            float* bs = Bs + st * STG;
            cpa16(as + row0 * PADW + kq, Ab0 + off);
            cpa16(as + (row0 + 64) * PADW + kq, Ab1 + off);
            cpa16(bs + row0 * PADW + kq, Bb0 + off);
            cpa16(bs + (row0 + 64) * PADW + kq, Bb1 + off);
            CP_COMMIT();
        }

        const float* as = As + (it & 1) * STG;
        const float* bs = Bs + (it & 1) * STG;
#pragma unroll
        for (int ks = 0; ks < 16; ks += 8) {
            uint32_t af[4][4], bf[4][2];
#pragma unroll
            for (int mt = 0; mt < 4; mt++) {
                const float* p = as + (wm + mt * 16 + r) * PADW + ks + c;
                af[mt][0] = f2tf(p[0]);
                af[mt][1] = f2tf(p[8 * PADW]);
                af[mt][2] = f2tf(p[4]);
                af[mt][3] = f2tf(p[8 * PADW + 4]);
            }
#pragma unroll
            for (int nt = 0; nt < 4; nt++) {
                const float* p = bs + (wn + nt * 8 + r) * PADW + ks + c;
                bf[nt][0] = f2tf(p[0]);
                bf[nt][1] = f2tf(p[4]);
            }
#pragma unroll
            for (int mt = 0; mt < 4; mt++)
#pragma unroll
                for (int nt = 0; nt < 4; nt++)
                    mma_tf32(acc[mt][nt][0], acc[mt][nt][1], acc[mt][nt][2], acc[mt][nt][3],
                             af[mt][0], af[mt][1], af[mt][2], af[mt][3],
                             bf[nt][0], bf[nt][1]);
        }
        __syncthreads();
    }

#pragma unroll
    for (int mt = 0; mt < 4; mt++) {
#pragma unroll
        for (int nt = 0; nt < 4; nt++) {
            float* p = C + (size_t)(m0 + wm + mt * 16 + r) * Dc + n0 + wn + nt * 8 + 2 * c;
            float2 v0, v1;
            v0.x = alpha * acc[mt][nt][0];
            v0.y = alpha * acc[mt][nt][1];
            v1.x = alpha * acc[mt][nt][2];
            v1.y = alpha * acc[mt][nt][3];
            *(float2*)p = v0;
            *(float2*)(p + 8 * Dc) = v1;
        }
    }
}

// single GEMM
__global__ __launch_bounds__(256, 2) void tgemm(const float* __restrict__ A,
                                                const float* __restrict__ Wt,
                                                float* __restrict__ C, float alpha) {
    __shared__ float As[2 * STG];
    __shared__ float Bs[2 * STG];
    gemm_body(A, Wt, C, alpha, blockIdx.x, blockIdx.y, As, Bs);
}

// batched 4-way GEMM (q, k, v, q_g share the A matrix g_xn)
__global__ __launch_bounds__(256, 2) void tgemm4(const float* __restrict__ A,
                                                 const float* __restrict__ w0,
                                                 const float* __restrict__ w1,
                                                 const float* __restrict__ w2,
                                                 const float* __restrict__ w3,
                                                 float* __restrict__ o0,
                                                 float* __restrict__ o1,
                                                 float* __restrict__ o2,
                                                 float* __restrict__ o3) {
    __shared__ float As[2 * STG];
    __shared__ float Bs[2 * STG];
    const float* Wt;
    float* C;
    switch (blockIdx.z) {
        case 0: Wt = w0; C = o0; break;
        case 1: Wt = w1; C = o1; break;
        case 2: Wt = w2; C = o2; break;
        default: Wt = w3; C = o3; break;
    }
    gemm_body(A, Wt, C, 1.0f, blockIdx.x, blockIdx.y, As, Bs);
}

// ---------------- gate ----------------
__global__ __launch_bounds__(512) void gate_k(const float* __restrict__ wg,
                                              const float* __restrict__ bg) {
    int row = blockIdx.x;
    int w = threadIdx.x >> 5;
    int lane = threadIdx.x & 31;
    const float* xr = g_xn + row * Dc;
    const float* wr = wg + w * Dc;
    float s = 0.f;
    for (int d = lane; d < Dc; d += 32) s += xr[d] * wr[d];
#pragma unroll
    for (int o = 16; o > 0; o >>= 1) s += __shfl_xor_sync(0xffffffffu, s, o);
    __shared__ float hs[16];
    if (lane == 0) hs[w] = 1.f / (1.f + __expf(-(s + bg[w])));
    __syncthreads();
    if (threadIdx.x == 0) {
        float m = 0.f;
#pragma unroll
        for (int h = 0; h < 16; h++) m += hs[h];
        g_gate[row] = m * (1.f / 16.f);
    }
}

// ---------------- RoPE (in place) ----------------
__global__ __launch_bounds__(256) void rope_k(float* __restrict__ p) {
    int gid = blockIdx.x * 256 + threadIdx.x;
    int row = gid >> 9;
    int rem = gid & 511;
    int h = rem >> 5;
    int i = rem & 31;
    int t = row & (Tc - 1);
    int base = row * Dc + h * 64 + i;
    float u1 = p[base];
    float u2 = p[base + 32];
    float fr = exp2f(-(float)i * 0.41524100184f);
    float ang = (float)t * fr;
    float cc, ss;
    __sincosf(ang, &ss, &cc);
    p[base] = u1 * cc - u2 * ss;
    p[base + 32] = u2 * cc + u1 * ss;
}

// ---------------- sliding-window attention ----------------
#define ATTN_SMEM ((64 * 68 * 2 + 128 * 65) * 4)
__global__ __launch_bounds__(128) void attn_k() {
    extern __shared__ float sm[];
    float* ks = sm;
    float* vs = sm + 64 * 68;
    float* ps = sm + 2 * 64 * 68;
    int tid = threadIdx.x;
    int q0 = blockIdx.x * 128;
    int h = blockIdx.y;
    int b = blockIdx.z;
    int tq = q0 + tid;

    const float* qbase = g_q + (size_t)(b * Tc + q0) * Dc + h * 64;
#pragma unroll 4
    for (int it = 0; it < 64; it++) {
        int id = it * 128 + tid;
        int r = id >> 6, d = id & 63;
        ps[r * 65 + d] = qbase[(size_t)r * Dc + d];
    }
    __syncthreads();
    float qv[64];
#pragma unroll
    for (int d = 0; d < 64; d++) qv[d] = ps[tid * 65 + d];
    __syncthreads();

    float m = -1e30f, l = 0.f;
    float acc[64];
#pragma unroll
    for (int d = 0; d < 64; d++) acc[d] = 0.f;

    int s_start = q0 - Wc;
    if (s_start < 0) s_start = 0;
    for (int s0 = s_start; s0 < q0 + 128; s0 += 64) {
        const float* kb = g_k + (size_t)(b * Tc + s0) * Dc + h * 64;
        const float* vb = g_v + (size_t)(b * Tc + s0) * Dc + h * 64;
#pragma unroll 4
        for (int it = 0; it < 32; it++) {
            int id = it * 128 + tid;
            int r = id >> 6, d = id & 63;
            ks[r * 68 + d] = kb[(size_t)r * Dc + d];
            vs[r * 68 + d] = vb[(size_t)r * Dc + d];
        }
        __syncthreads();

        float tmax = -1e30f;
        for (int j = 0; j < 64; j++) {
            const float4* k4 = (const float4*)(ks + j * 68);
            float s = 0.f;
#pragma unroll
            for (int d4 = 0; d4 < 16; d4++) {
                float4 kvv = k4[d4];
                s += qv[d4 * 4 + 0] * kvv.x;
                s += qv[d4 * 4 + 1] * kvv.y;
                s += qv[d4 * 4 + 2] * kvv.z;
                s += qv[d4 * 4 + 3] * kvv.w;
            }
            s *= 0.125f;
            int sg = s0 + j;
            if (sg > tq || sg < tq - Wc) s = -1e30f;
            ps[tid * 65 + j] = s;
            tmax = fmaxf(tmax, s);
        }
        float mnew = fmaxf(m, tmax);
        float corr = __expf(m - mnew);
        l *= corr;
#pragma unroll
        for (int d = 0; d < 64; d++) acc[d] *= corr;
        for (int j = 0; j < 64; j++) {
            float sv = ps[tid * 65 + j];
            float p = (sv > -1e29f) ? __expf(sv - mnew) : 0.f;
            l += p;
            const float4* v4 = (const float4*)(vs + j * 68);
#pragma unroll
            for (int d4 = 0; d4 < 16; d4++) {
                float4 vvv = v4[d4];
                acc[d4 * 4 + 0] += p * vvv.x;
                acc[d4 * 4 + 1] += p * vvv.y;
                acc[d4 * 4 + 2] += p * vvv.z;
                acc[d4 * 4 + 3] += p * vvv.w;
            }
        }
        m = mnew;
        __syncthreads();
    }
    float inv = 1.f / l;
    float* ob = g_local + (size_t)(b * Tc + tq) * Dc + h * 64;
#pragma unroll
    for (int d = 0; d < 64; d++) ob[d] = acc[d] * inv;
}

// ---------------- retrieval ----------------
__global__ __launch_bounds__(256) void retr_k(const float* __restrict__ state,
                                              const int* __restrict__ ids,
                                              const float* __restrict__ bank) {
    __shared__ float st[64 * 64];
    __shared__ float qs[4][64];
    int tc = blockIdx.x;
    int h = blockIdx.y;
    int b = blockIdx.z;
    int tid = threadIdx.x;
    const float* sb = state + (size_t)((b * Hc + h) * 64) * 64;
    for (int i = tid; i < 4096; i += 256) st[i] = sb[i];
    __syncthreads();
    int tloc = tid >> 6;
    int kk = tid & 63;
    for (int t0 = tc * 128; t0 < tc * 128 + 128; t0 += 4) {
        int t = t0 + tloc;
        int ii = ids[b * Tc + t] - CUE_C;
        float val;
        if (ii >= 0 && ii < BANK_C)
            val = bank[(size_t)(h * BANK_C + ii) * 64 + kk];
        else
            val = g_qg[(size_t)(b * Tc + t) * Dc + h * 64 + kk];
        qs[tloc][kk] = val;
        __syncthreads();
        float sum = 0.f;
#pragma unroll
        for (int k2 = 0; k2 < 64; k2++) sum += st[k2 * 64 + kk] * qs[tloc][k2];
        g_ret[(size_t)(b * Tc + t) * Dc + h * 64 + kk] = sum;
        __syncthreads();
    }
}

// ---------------- final combine ----------------
__global__ __launch_bounds__(256) void combine_k(const float* __restrict__ x,
                                                 float* __restrict__ out) {
    int idx = blockIdx.x * 256 + threadIdx.x;
    int row = idx >> 8;
    float g = g_gate[row];
    float4 xv = ((const float4*)x)[idx];
    float4 lv = ((const float4*)g_localO)[idx];
    float4 rv = ((const float4*)g_ro)[idx];
    float4 o;
    o.x = xv.x + lv.x + g * rv.x;
    o.y = xv.y + lv.y + g * rv.y;
    o.z = xv.z + lv.z + g * rv.z;
    o.w = xv.w + lv.w + g * rv.w;
    ((float4*)out)[idx] = o;
}

// ---------------- launch ----------------
extern "C" void kernel_launch(void* const* d_in, const int* in_sizes, int n_in,
                              void* d_out, int out_size) {
    const float* x = (const float*)d_in[0];
    const float* gdn = (const float*)d_in[1];
    const int* ids = (const int*)d_in[2];
    const float* bank = (const float*)d_in[3];
    const float* normw = (const float*)d_in[4];
    const float* wq = (const float*)d_in[5];
    const float* wk = (const float*)d_in[6];
    const float* wv = (const float*)d_in[7];
    const float* wo = (const float*)d_in[8];
    const float* wgq = (const float*)d_in[9];
    const float* wro = (const float*)d_in[10];
    const float* wgate = (const float*)d_in[11];
    const float* bgate = (const float*)d_in[12];
    float* out = (float*)d_out;

    float *xn, *q, *k, *v, *qg, *loc, *locO, *ret, *ro;
    cudaGetSymbolAddress((void**)&xn, g_xn);
    cudaGetSymbolAddress((void**)&q, g_q);
    cudaGetSymbolAddress((void**)&k, g_k);
    cudaGetSymbolAddress((void**)&v, g_v);
    cudaGetSymbolAddress((void**)&qg, g_qg);
    cudaGetSymbolAddress((void**)&loc, g_local);
    cudaGetSymbolAddress((void**)&locO, g_localO);
    cudaGetSymbolAddress((void**)&ret, g_ret);
    cudaGetSymbolAddress((void**)&ro, g_ro);

    cudaFuncSetAttribute(attn_k, cudaFuncAttributeMaxDynamicSharedMemorySize,
                         ATTN_SMEM);

    rmsnorm_k<<<MROWS, 256>>>(x, normw);

    dim3 gg4(Dc / 128, MROWS / 128, 4);  // (8, 32, 4) = 1024 blocks
    tgemm4<<<gg4, 256>>>(xn, wq, wk, wv, wgq, q, k, v, qg);

    gate_k<<<MROWS, 512>>>(wgate, bgate);

    rope_k<<<(MROWS * Hc * 32) / 256, 256>>>(q);
    rope_k<<<(MROWS * Hc * 32) / 256, 256>>>(k);

    attn_k<<<dim3(Tc / 128, Hc, Bc), 128, ATTN_SMEM>>>();

    dim3 gg(Dc / 128, MROWS / 128);
    tgemm<<<gg, 256>>>(loc, wo, locO, 0.3f);

    retr_k<<<dim3(Tc / 128, Hc, Bc), 256>>>(gdn, ids, bank);

    tgemm<<<gg, 256>>>(ret, wro, ro, 1.0f);

    combine_k<<<(MROWS * Dc / 4) / 256, 256>>>(x, out);
}

// round 10
// speedup vs baseline: 2.1312x; 1.0164x over previous
#include <cuda_runtime.h>
#include <math.h>
#include <stdint.h>

// Problem dims
#define Bc 2
#define Tc 2048
#define Dc 1024
#define Hc 16
#define Kc 64
#define Vc 64
#define Wc 256
#define MROWS (Bc * Tc)          // 4096
#define CUE_C 50250
#define BANK_C 64

// ---------------- scratch (device globals; no allocs allowed) ----------------
__device__ float g_xn[MROWS * Dc];
__device__ float g_q[MROWS * Dc];
__device__ float g_k[MROWS * Dc];
__device__ float g_v[MROWS * Dc];
__device__ float g_qg[MROWS * Dc];
__device__ float g_local[MROWS * Dc];
__device__ float g_localO[MROWS * Dc];
__device__ float g_ret[MROWS * Dc];
__device__ float g_ro[MROWS * Dc];
__device__ float g_gate[MROWS];
__device__ float g_wr[6 * Dc * Dc];   // tf32-rounded weights

// ---------------- helpers ----------------
__device__ __forceinline__ float tf32r(float f) {
    uint32_t u;
    asm("cvt.rna.tf32.f32 %0, %1;" : "=r"(u) : "f"(f));
    return __uint_as_float(u);
}

__device__ __forceinline__ void mma_tf32(float& d0, float& d1, float& d2, float& d3,
                                         uint32_t a0, uint32_t a1, uint32_t a2, uint32_t a3,
                                         uint32_t b0, uint32_t b1) {
    asm volatile(
        "mma.sync.aligned.m16n8k8.row.col.f32.tf32.tf32.f32 "
        "{%0,%1,%2,%3}, {%4,%5,%6,%7}, {%8,%9}, {%0,%1,%2,%3};\n"
        : "+f"(d0), "+f"(d1), "+f"(d2), "+f"(d3)
        : "r"(a0), "r"(a1), "r"(a2), "r"(a3), "r"(b0), "r"(b1));
}

__device__ __forceinline__ void cpa16(void* smem, const void* gmem) {
    uint32_t s = (uint32_t)__cvta_generic_to_shared(smem);
    asm volatile("cp.async.cg.shared.global [%0], [%1], 16;\n" ::"r"(s), "l"(gmem));
}
#define CP_COMMIT() asm volatile("cp.async.commit_group;\n" ::: "memory")
#define CP_WAIT2() asm volatile("cp.async.wait_group 2;\n" ::: "memory")

// ---------------- weight rounding (once per call; memory-bound) -------------
__global__ __launch_bounds__(256) void roundw_k(const float* __restrict__ w0,
                                                const float* __restrict__ w1,
                                                const float* __restrict__ w2,
                                                const float* __restrict__ w3,
                                                const float* __restrict__ w4,
                                                const float* __restrict__ w5) {
    int gid = blockIdx.x * 256 + threadIdx.x;       // 6*1M/4 = 1572864
    int sel = gid >> 18;                            // which weight
    int off = gid & 262143;                         // float4 index within
    const float* w;
    switch (sel) {
        case 0: w = w0; break;
        case 1: w = w1; break;
        case 2: w = w2; break;
        case 3: w = w3; break;
        case 4: w = w4; break;
        default: w = w5; break;
    }
    float4 v = ((const float4*)w)[off];
    v.x = tf32r(v.x); v.y = tf32r(v.y); v.z = tf32r(v.z); v.w = tf32r(v.w);
    ((float4*)(g_wr + ((size_t)sel << 20)))[off] = v;
}

// ---------------- RMSNorm (outputs tf32-rounded) ----------------
__global__ __launch_bounds__(256) void rmsnorm_k(const float* __restrict__ x,
                                                 const float* __restrict__ w) {
    int row = blockIdx.x;
    int tid = threadIdx.x;
    const float4* xr = (const float4*)(x + row * Dc);
    float4 vv = xr[tid];
    float s = vv.x * vv.x + vv.y * vv.y + vv.z * vv.z + vv.w * vv.w;
    __shared__ float red[256];
    red[tid] = s;
    __syncthreads();
    for (int o = 128; o > 0; o >>= 1) {
        if (tid < o) red[tid] += red[tid + o];
        __syncthreads();
    }
    float inv = rsqrtf(red[0] * (1.0f / Dc) + 1e-6f);
    float4 wv = ((const float4*)w)[tid];
    float4 o;
    o.x = tf32r(vv.x * inv * wv.x);
    o.y = tf32r(vv.y * inv * wv.y);
    o.z = tf32r(vv.z * inv * wv.z);
    o.w = tf32r(vv.w * inv * wv.w);
    ((float4*)(g_xn + row * Dc))[tid] = o;
}

// ---------------- tf32 tensor-core GEMM, 4-stage cp.async pipeline ----------
// A and W are pre-rounded to tf32-representable f32; inner loop = LDS + HMMA.
#define PADW 20
#define STG (128 * PADW)
#define NSTAGE 4

__device__ __forceinline__ void gemm_body(const float* __restrict__ A,
                                          const float* __restrict__ Wt,
                                          float* __restrict__ C, float alpha,
                                          int bx, int by,
                                          float* As, float* Bs) {
    int tid = threadIdx.x;
    int lane = tid & 31;
    int wid = tid >> 5;
    int wm = (wid >> 2) * 64;
    int wn = (wid & 3) * 32;
    int r = lane >> 2;
    int c = lane & 3;
    int m0 = by * 128;
    int n0 = bx * 128;

    int row0 = tid >> 2;        // 0..63
    int kq = (tid & 3) * 4;
    const float* Ab0 = A + (size_t)(m0 + row0) * Dc + kq;
    const float* Ab1 = A + (size_t)(m0 + row0 + 64) * Dc + kq;
    const float* Bb0 = Wt + (size_t)(n0 + row0) * Dc + kq;
    const float* Bb1 = Wt + (size_t)(n0 + row0 + 64) * Dc + kq;

    float acc[4][4][4];
#pragma unroll
    for (int i = 0; i < 4; i++)
#pragma unroll
        for (int j = 0; j < 4; j++)
#pragma unroll
            for (int e = 0; e < 4; e++) acc[i][j][e] = 0.f;

    const int nIter = Dc / 16;  // 64

#define FILL(st, koff)                                          \
    do {                                                        \
        float* as_ = As + (st) * STG;                           \
        float* bs_ = Bs + (st) * STG;                           \
        cpa16(as_ + row0 * PADW + kq, Ab0 + (koff));            \
        cpa16(as_ + (row0 + 64) * PADW + kq, Ab1 + (koff));     \
        cpa16(bs_ + row0 * PADW + kq, Bb0 + (koff));            \
        cpa16(bs_ + (row0 + 64) * PADW + kq, Bb1 + (koff));     \
    } while (0)

    // prologue: stages 0..2
    FILL(0, 0); CP_COMMIT();
    FILL(1, 16); CP_COMMIT();
    FILL(2, 32); CP_COMMIT();

    for (int it = 0; it < nIter; it++) {
        CP_WAIT2();            // group for k-iter `it` complete
        __syncthreads();

        if (it + 3 < nIter) FILL((it + 3) & 3, (it + 3) * 16);
        CP_COMMIT();           // unconditional: keeps group count uniform

        const uint32_t* as = (const uint32_t*)(As + (it & 3) * STG);
        const uint32_t* bs = (const uint32_t*)(Bs + (it & 3) * STG);
#pragma unroll
        for (int ks = 0; ks < 16; ks += 8) {
            uint32_t af[4][4], bf[4][2];
#pragma unroll
            for (int mt = 0; mt < 4; mt++) {
                const uint32_t* p = as + (wm + mt * 16 + r) * PADW + ks + c;
                af[mt][0] = p[0];
                af[mt][1] = p[8 * PADW];
                af[mt][2] = p[4];
                af[mt][3] = p[8 * PADW + 4];
            }
#pragma unroll
            for (int nt = 0; nt < 4; nt++) {
                const uint32_t* p = bs + (wn + nt * 8 + r) * PADW + ks + c;
                bf[nt][0] = p[0];
                bf[nt][1] = p[4];
            }
#pragma unroll
            for (int mt = 0; mt < 4; mt++)
#pragma unroll
                for (int nt = 0; nt < 4; nt++)
                    mma_tf32(acc[mt][nt][0], acc[mt][nt][1], acc[mt][nt][2], acc[mt][nt][3],
                             af[mt][0], af[mt][1], af[mt][2], af[mt][3],
                             bf[nt][0], bf[nt][1]);
        }
        __syncthreads();
    }
#undef FILL

#pragma unroll
    for (int mt = 0; mt < 4; mt++) {
#pragma unroll
        for (int nt = 0; nt < 4; nt++) {
            float* p = C + (size_t)(m0 + wm + mt * 16 + r) * Dc + n0 + wn + nt * 8 + 2 * c;
            float2 v0, v1;
            v0.x = alpha * acc[mt][nt][0];
            v0.y = alpha * acc[mt][nt][1];
            v1.x = alpha * acc[mt][nt][2];
            v1.y = alpha * acc[mt][nt][3];
            *(float2*)p = v0;
            *(float2*)(p + 8 * Dc) = v1;
        }
    }
}

__global__ __launch_bounds__(256, 2) void tgemm(const float* __restrict__ A,
                                                const float* __restrict__ Wt,
                                                float* __restrict__ C, float alpha) {
    __shared__ float As[NSTAGE * STG];
    __shared__ float Bs[NSTAGE * STG];
    gemm_body(A, Wt, C, alpha, blockIdx.x, blockIdx.y, As, Bs);
}

// batched 4-way GEMM (q, k, v, q_g share the A matrix g_xn)
__global__ __launch_bounds__(256, 2) void tgemm4(const float* __restrict__ A,
                                                 float* __restrict__ o0,
                                                 float* __restrict__ o1,
                                                 float* __restrict__ o2,
                                                 float* __restrict__ o3) {
    __shared__ float As[NSTAGE * STG];
    __shared__ float Bs[NSTAGE * STG];
    const float* Wt = g_wr + ((size_t)blockIdx.z << 20);
    float* C;
    switch (blockIdx.z) {
        case 0: C = o0; break;
        case 1: C = o1; break;
        case 2: C = o2; break;
        default: C = o3; break;
    }
    gemm_body(A, Wt, C, 1.0f, blockIdx.x, blockIdx.y, As, Bs);
}

// ---------------- gate ----------------
__global__ __launch_bounds__(512) void gate_k(const float* __restrict__ wg,
                                              const float* __restrict__ bg) {
    int row = blockIdx.x;
    int w = threadIdx.x >> 5;
    int lane = threadIdx.x & 31;
    const float* xr = g_xn + row * Dc;
    const float* wr = wg + w * Dc;
    float s = 0.f;
    for (int d = lane; d < Dc; d += 32) s += xr[d] * wr[d];
#pragma unroll
    for (int o = 16; o > 0; o >>= 1) s += __shfl_xor_sync(0xffffffffu, s, o);
    __shared__ float hs[16];
    if (lane == 0) hs[w] = 1.f / (1.f + __expf(-(s + bg[w])));
    __syncthreads();
    if (threadIdx.x == 0) {
        float m = 0.f;
#pragma unroll
        for (int h = 0; h < 16; h++) m += hs[h];
        g_gate[row] = m * (1.f / 16.f);
    }
}

// ---------------- RoPE (in place; q and k in one launch) ----------------
__global__ __launch_bounds__(256) void rope_k(float* __restrict__ pq,
                                              float* __restrict__ pk) {
    float* p = blockIdx.y ? pk : pq;
    int gid = blockIdx.x * 256 + threadIdx.x;
    int row = gid >> 9;
    int rem = gid & 511;
    int h = rem >> 5;
    int i = rem & 31;
    int t = row & (Tc - 1);
    int base = row * Dc + h * 64 + i;
    float u1 = p[base];
    float u2 = p[base + 32];
    float fr = exp2f(-(float)i * 0.41524100184f);
    float ang = (float)t * fr;
    float cc, ss;
    __sincosf(ang, &ss, &cc);
    p[base] = u1 * cc - u2 * ss;
    p[base + 32] = u2 * cc + u1 * ss;
}

// ---------------- sliding-window attention (output tf32-rounded) ------------
#define ATTN_SMEM ((64 * 68 * 2 + 128 * 65) * 4)
__global__ __launch_bounds__(128) void attn_k() {
    extern __shared__ float sm[];
    float* ks = sm;
    float* vs = sm + 64 * 68;
    float* ps = sm + 2 * 64 * 68;
    int tid = threadIdx.x;
    int q0 = blockIdx.x * 128;
    int h = blockIdx.y;
    int b = blockIdx.z;
    int tq = q0 + tid;

    const float* qbase = g_q + (size_t)(b * Tc + q0) * Dc + h * 64;
#pragma unroll 4
    for (int it = 0; it < 64; it++) {
        int id = it * 128 + tid;
        int r = id >> 6, d = id & 63;
        ps[r * 65 + d] = qbase[(size_t)r * Dc + d];
    }
    __syncthreads();
    float qv[64];
#pragma unroll
    for (int d = 0; d < 64; d++) qv[d] = ps[tid * 65 + d];
    __syncthreads();

    float m = -1e30f, l = 0.f;
    float acc[64];
#pragma unroll
    for (int d = 0; d < 64; d++) acc[d] = 0.f;

    int s_start = q0 - Wc;
    if (s_start < 0) s_start = 0;
    for (int s0 = s_start; s0 < q0 + 128; s0 += 64) {
        const float* kb = g_k + (size_t)(b * Tc + s0) * Dc + h * 64;
        const float* vb = g_v + (size_t)(b * Tc + s0) * Dc + h * 64;
#pragma unroll 4
        for (int it = 0; it < 32; it++) {
            int id = it * 128 + tid;
            int r = id >> 6, d = id & 63;
            ks[r * 68 + d] = kb[(size_t)r * Dc + d];
            vs[r * 68 + d] = vb[(size_t)r * Dc + d];
        }
        __syncthreads();

        float tmax = -1e30f;
        for (int j = 0; j < 64; j++) {
            const float4* k4 = (const float4*)(ks + j * 68);
            float s = 0.f;
#pragma unroll
            for (int d4 = 0; d4 < 16; d4++) {
                float4 kvv = k4[d4];
                s += qv[d4 * 4 + 0] * kvv.x;
                s += qv[d4 * 4 + 1] * kvv.y;
                s += qv[d4 * 4 + 2] * kvv.z;
                s += qv[d4 * 4 + 3] * kvv.w;
            }
            s *= 0.125f;
            int sg = s0 + j;
            if (sg > tq || sg < tq - Wc) s = -1e30f;
            ps[tid * 65 + j] = s;
            tmax = fmaxf(tmax, s);
        }
        float mnew = fmaxf(m, tmax);
        float corr = __expf(m - mnew);
        l *= corr;
#pragma unroll
        for (int d = 0; d < 64; d++) acc[d] *= corr;
        for (int j = 0; j < 64; j++) {
            float sv = ps[tid * 65 + j];
            float p = (sv > -1e29f) ? __expf(sv - mnew) : 0.f;
            l += p;
            const float4* v4 = (const float4*)(vs + j * 68);
#pragma unroll
            for (int d4 = 0; d4 < 16; d4++) {
                float4 vvv = v4[d4];
                acc[d4 * 4 + 0] += p * vvv.x;
                acc[d4 * 4 + 1] += p * vvv.y;
                acc[d4 * 4 + 2] += p * vvv.z;
                acc[d4 * 4 + 3] += p * vvv.w;
            }
        }
        m = mnew;
        __syncthreads();
    }
    float inv = 1.f / l;
    float* ob = g_local + (size_t)(b * Tc + tq) * Dc + h * 64;
#pragma unroll
    for (int d = 0; d < 64; d++) ob[d] = tf32r(acc[d] * inv);
}

// ---------------- retrieval (output tf32-rounded) ----------------
__global__ __launch_bounds__(256) void retr_k(const float* __restrict__ state,
                                              const int* __restrict__ ids,
                                              const float* __restrict__ bank) {
    __shared__ float st[64 * 64];
    __shared__ float qs[4][64];
    int tc = blockIdx.x;
    int h = blockIdx.y;
    int b = blockIdx.z;
    int tid = threadIdx.x;
    const float* sb = state + (size_t)((b * Hc + h) * 64) * 64;
    for (int i = tid; i < 4096; i += 256) st[i] = sb[i];
    __syncthreads();
    int tloc = tid >> 6;
    int kk = tid & 63;
    for (int t0 = tc * 128; t0 < tc * 128 + 128; t0 += 4) {
        int t = t0 + tloc;
        int ii = ids[b * Tc + t] - CUE_C;
        float val;
        if (ii >= 0 && ii < BANK_C)
            val = bank[(size_t)(h * BANK_C + ii) * 64 + kk];
        else
            val = g_qg[(size_t)(b * Tc + t) * Dc + h * 64 + kk];
        qs[tloc][kk] = val;
        __syncthreads();
        float sum = 0.f;
#pragma unroll
        for (int k2 = 0; k2 < 64; k2++) sum += st[k2 * 64 + kk] * qs[tloc][k2];
        g_ret[(size_t)(b * Tc + t) * Dc + h * 64 + kk] = tf32r(sum);
        __syncthreads();
    }
}

// ---------------- final combine ----------------
__global__ __launch_bounds__(256) void combine_k(const float* __restrict__ x,
                                                 float* __restrict__ out) {
    int idx = blockIdx.x * 256 + threadIdx.x;
    int row = idx >> 8;
    float g = g_gate[row];
    float4 xv = ((const float4*)x)[idx];
    float4 lv = ((const float4*)g_localO)[idx];
    float4 rv = ((const float4*)g_ro)[idx];
    float4 o;
    o.x = xv.x + lv.x + g * rv.x;
    o.y = xv.y + lv.y + g * rv.y;
    o.z = xv.z + lv.z + g * rv.z;
    o.w = xv.w + lv.w + g * rv.w;
    ((float4*)out)[idx] = o;
}

// ---------------- launch ----------------
extern "C" void kernel_launch(void* const* d_in, const int* in_sizes, int n_in,
                              void* d_out, int out_size) {
    const float* x = (const float*)d_in[0];
    const float* gdn = (const float*)d_in[1];
    const int* ids = (const int*)d_in[2];
    const float* bank = (const float*)d_in[3];
    const float* normw = (const float*)d_in[4];
    const float* wq = (const float*)d_in[5];
    const float* wk = (const float*)d_in[6];
    const float* wv = (const float*)d_in[7];
    const float* wo = (const float*)d_in[8];
    const float* wgq = (const float*)d_in[9];
    const float* wro = (const float*)d_in[10];
    const float* wgate = (const float*)d_in[11];
    const float* bgate = (const float*)d_in[12];
    float* out = (float*)d_out;

    float *xn, *q, *k, *v, *qg, *loc, *locO, *ret, *ro, *wr;
    cudaGetSymbolAddress((void**)&xn, g_xn);
    cudaGetSymbolAddress((void**)&q, g_q);
    cudaGetSymbolAddress((void**)&k, g_k);
    cudaGetSymbolAddress((void**)&v, g_v);
    cudaGetSymbolAddress((void**)&qg, g_qg);
    cudaGetSymbolAddress((void**)&loc, g_local);
    cudaGetSymbolAddress((void**)&locO, g_localO);
    cudaGetSymbolAddress((void**)&ret, g_ret);
    cudaGetSymbolAddress((void**)&ro, g_ro);
    cudaGetSymbolAddress((void**)&wr, g_wr);

    cudaFuncSetAttribute(attn_k, cudaFuncAttributeMaxDynamicSharedMemorySize,
                         ATTN_SMEM);

    // round weights: order matches g_wr slots 0..5
    roundw_k<<<6144, 256>>>(wq, wk, wv, wgq, wo, wro);

    rmsnorm_k<<<MROWS, 256>>>(x, normw);

    dim3 gg4(Dc / 128, MROWS / 128, 4);  // 1024 blocks
    tgemm4<<<gg4, 256>>>(xn, q, k, v, qg);

    gate_k<<<MROWS, 512>>>(wgate, bgate);

    rope_k<<<dim3((MROWS * Hc * 32) / 256, 2), 256>>>(q, k);

    attn_k<<<dim3(Tc / 128, Hc, Bc), 128, ATTN_SMEM>>>();

    dim3 gg(Dc / 128, MROWS / 128);
    tgemm<<<gg, 256>>>(loc, wr + ((size_t)4 << 20), locO, 0.3f);

    retr_k<<<dim3(Tc / 128, Hc, Bc), 256>>>(gdn, ids, bank);

    tgemm<<<gg, 256>>>(ret, wr + ((size_t)5 << 20), ro, 1.0f);

    combine_k<<<(MROWS * Dc / 4) / 256, 256>>>(x, out);
}

// round 14
// speedup vs baseline: 2.2768x; 1.0683x over previous
#include <cuda_runtime.h>
#include <math.h>
#include <stdint.h>

// Problem dims
#define Bc 2
#define Tc 2048
#define Dc 1024
#define Hc 16
#define Kc 64
#define Vc 64
#define Wc 256
#define MROWS (Bc * Tc)          // 4096
#define CUE_C 50250
#define BANK_C 64

typedef unsigned long long u64;

// ---------------- scratch (device globals; no allocs allowed) ----------------
__device__ float g_xn[MROWS * Dc];
__device__ float g_q[MROWS * Dc];
__device__ float g_k[MROWS * Dc];
__device__ float g_v[MROWS * Dc];
__device__ float g_qg[MROWS * Dc];
__device__ float g_local[MROWS * Dc];
__device__ float g_localO[MROWS * Dc];
__device__ float g_ret[MROWS * Dc];
__device__ float g_ro[MROWS * Dc];
__device__ float g_gate[MROWS];
__device__ float g_wr[6 * Dc * Dc];   // tf32-rounded weights

// ---------------- helpers ----------------
__device__ __forceinline__ float tf32r(float f) {
    uint32_t u;
    asm("cvt.rna.tf32.f32 %0, %1;" : "=r"(u) : "f"(f));
    return __uint_as_float(u);
}

__device__ __forceinline__ u64 pack2(float lo, float hi) {
    u64 r;
    asm("mov.b64 %0, {%1, %2};" : "=l"(r) : "f"(lo), "f"(hi));
    return r;
}
__device__ __forceinline__ void unpack2(u64 v, float& lo, float& hi) {
    asm("mov.b64 {%0, %1}, %2;" : "=f"(lo), "=f"(hi) : "l"(v));
}
__device__ __forceinline__ u64 fma2(u64 a, u64 b, u64 c) {
    u64 d;
    asm("fma.rn.f32x2 %0, %1, %2, %3;" : "=l"(d) : "l"(a), "l"(b), "l"(c));
    return d;
}
__device__ __forceinline__ u64 mul2(u64 a, u64 b) {
    u64 d;
    asm("mul.rn.f32x2 %0, %1, %2;" : "=l"(d) : "l"(a), "l"(b));
    return d;
}

__device__ __forceinline__ void mma_tf32(float& d0, float& d1, float& d2, float& d3,
                                         uint32_t a0, uint32_t a1, uint32_t a2, uint32_t a3,
                                         uint32_t b0, uint32_t b1) {
    asm volatile(
        "mma.sync.aligned.m16n8k8.row.col.f32.tf32.tf32.f32 "
        "{%0,%1,%2,%3}, {%4,%5,%6,%7}, {%8,%9}, {%0,%1,%2,%3};\n"
        : "+f"(d0), "+f"(d1), "+f"(d2), "+f"(d3)
        : "r"(a0), "r"(a1), "r"(a2), "r"(a3), "r"(b0), "r"(b1));
}

__device__ __forceinline__ void cpa16(void* smem, const void* gmem) {
    uint32_t s = (uint32_t)__cvta_generic_to_shared(smem);
    asm volatile("cp.async.cg.shared.global [%0], [%1], 16;\n" ::"r"(s), "l"(gmem));
}
#define CP_COMMIT() asm volatile("cp.async.commit_group;\n" ::: "memory")
#define CP_WAIT2() asm volatile("cp.async.wait_group 2;\n" ::: "memory")

// ---------------- weight rounding (once per call; memory-bound) -------------
__global__ __launch_bounds__(256) void roundw_k(const float* __restrict__ w0,
                                                const float* __restrict__ w1,
                                                const float* __restrict__ w2,
                                                const float* __restrict__ w3,
                                                const float* __restrict__ w4,
                                                const float* __restrict__ w5) {
    int gid = blockIdx.x * 256 + threadIdx.x;
    int sel = gid >> 18;
    int off = gid & 262143;
    const float* w;
    switch (sel) {
        case 0: w = w0; break;
        case 1: w = w1; break;
        case 2: w = w2; break;
        case 3: w = w3; break;
        case 4: w = w4; break;
        default: w = w5; break;
    }
    float4 v = ((const float4*)w)[off];
    v.x = tf32r(v.x); v.y = tf32r(v.y); v.z = tf32r(v.z); v.w = tf32r(v.w);
    ((float4*)(g_wr + ((size_t)sel << 20)))[off] = v;
}

// ---------------- RMSNorm (outputs tf32-rounded) ----------------
__global__ __launch_bounds__(256) void rmsnorm_k(const float* __restrict__ x,
                                                 const float* __restrict__ w) {
    int row = blockIdx.x;
    int tid = threadIdx.x;
    const float4* xr = (const float4*)(x + row * Dc);
    float4 vv = xr[tid];
    float s = vv.x * vv.x + vv.y * vv.y + vv.z * vv.z + vv.w * vv.w;
    __shared__ float red[256];
    red[tid] = s;
    __syncthreads();
    for (int o = 128; o > 0; o >>= 1) {
        if (tid < o) red[tid] += red[tid + o];
        __syncthreads();
    }
    float inv = rsqrtf(red[0] * (1.0f / Dc) + 1e-6f);
    float4 wv = ((const float4*)w)[tid];
    float4 o;
    o.x = tf32r(vv.x * inv * wv.x);
    o.y = tf32r(vv.y * inv * wv.y);
    o.z = tf32r(vv.z * inv * wv.z);
    o.w = tf32r(vv.w * inv * wv.w);
    ((float4*)(g_xn + row * Dc))[tid] = o;
}

// ---------------- tf32 tensor-core GEMM, 4-stage cp.async pipeline ----------
#define PADW 20
#define STG (128 * PADW)
#define NSTAGE 4

__device__ __forceinline__ void gemm_body(const float* __restrict__ A,
                                          const float* __restrict__ Wt,
                                          float* __restrict__ C, float alpha,
                                          int bx, int by,
                                          float* As, float* Bs) {
    int tid = threadIdx.x;
    int lane = tid & 31;
    int wid = tid >> 5;
    int wm = (wid >> 2) * 64;
    int wn = (wid & 3) * 32;
    int r = lane >> 2;
    int c = lane & 3;
    int m0 = by * 128;
    int n0 = bx * 128;

    int row0 = tid >> 2;
    int kq = (tid & 3) * 4;
    const float* Ab0 = A + (size_t)(m0 + row0) * Dc + kq;
    const float* Ab1 = A + (size_t)(m0 + row0 + 64) * Dc + kq;
    const float* Bb0 = Wt + (size_t)(n0 + row0) * Dc + kq;
    const float* Bb1 = Wt + (size_t)(n0 + row0 + 64) * Dc + kq;

    float acc[4][4][4];
#pragma unroll
    for (int i = 0; i < 4; i++)
#pragma unroll
        for (int j = 0; j < 4; j++)
#pragma unroll
            for (int e = 0; e < 4; e++) acc[i][j][e] = 0.f;

    const int nIter = Dc / 16;

#define FILL(st, koff)                                          \
    do {                                                        \
        float* as_ = As + (st) * STG;                           \
        float* bs_ = Bs + (st) * STG;                           \
        cpa16(as_ + row0 * PADW + kq, Ab0 + (koff));            \
        cpa16(as_ + (row0 + 64) * PADW + kq, Ab1 + (koff));     \
        cpa16(bs_ + row0 * PADW + kq, Bb0 + (koff));            \
        cpa16(bs_ + (row0 + 64) * PADW + kq, Bb1 + (koff));     \
    } while (0)

    FILL(0, 0); CP_COMMIT();
    FILL(1, 16); CP_COMMIT();
    FILL(2, 32); CP_COMMIT();

    for (int it = 0; it < nIter; it++) {
        CP_WAIT2();
        __syncthreads();

        if (it + 3 < nIter) FILL((it + 3) & 3, (it + 3) * 16);
        CP_COMMIT();

        const uint32_t* as = (const uint32_t*)(As + (it & 3) * STG);
        const uint32_t* bs = (const uint32_t*)(Bs + (it & 3) * STG);
#pragma unroll
        for (int ks = 0; ks < 16; ks += 8) {
            uint32_t af[4][4], bf[4][2];
#pragma unroll
            for (int mt = 0; mt < 4; mt++) {
                const uint32_t* p = as + (wm + mt * 16 + r) * PADW + ks + c;
                af[mt][0] = p[0];
                af[mt][1] = p[8 * PADW];
                af[mt][2] = p[4];
                af[mt][3] = p[8 * PADW + 4];
            }
#pragma unroll
            for (int nt = 0; nt < 4; nt++) {
                const uint32_t* p = bs + (wn + nt * 8 + r) * PADW + ks + c;
                bf[nt][0] = p[0];
                bf[nt][1] = p[4];
            }
#pragma unroll
            for (int mt = 0; mt < 4; mt++)
#pragma unroll
                for (int nt = 0; nt < 4; nt++)
                    mma_tf32(acc[mt][nt][0], acc[mt][nt][1], acc[mt][nt][2], acc[mt][nt][3],
                             af[mt][0], af[mt][1], af[mt][2], af[mt][3],
                             bf[nt][0], bf[nt][1]);
        }
        __syncthreads();
    }
#undef FILL

#pragma unroll
    for (int mt = 0; mt < 4; mt++) {
#pragma unroll
        for (int nt = 0; nt < 4; nt++) {
            float* p = C + (size_t)(m0 + wm + mt * 16 + r) * Dc + n0 + wn + nt * 8 + 2 * c;
            float2 v0, v1;
            v0.x = alpha * acc[mt][nt][0];
            v0.y = alpha * acc[mt][nt][1];
            v1.x = alpha * acc[mt][nt][2];
            v1.y = alpha * acc[mt][nt][3];
            *(float2*)p = v0;
            *(float2*)(p + 8 * Dc) = v1;
        }
    }
}

// batched 4-way GEMM (q, k, v, q_g share the A matrix g_xn)
__global__ __launch_bounds__(256, 2) void tgemm4(const float* __restrict__ A,
                                                 float* __restrict__ o0,
                                                 float* __restrict__ o1,
                                                 float* __restrict__ o2,
                                                 float* __restrict__ o3) {
    __shared__ float As[NSTAGE * STG];
    __shared__ float Bs[NSTAGE * STG];
    const float* Wt = g_wr + ((size_t)blockIdx.z << 20);
    float* C;
    switch (blockIdx.z) {
        case 0: C = o0; break;
        case 1: C = o1; break;
        case 2: C = o2; break;
        default: C = o3; break;
    }
    gemm_body(A, Wt, C, 1.0f, blockIdx.x, blockIdx.y, As, Bs);
}

// batched 2-way GEMM for the tail: slot0 loc@wo (alpha .3), slot1 ret@wro
__global__ __launch_bounds__(256, 2) void tgemm2(const float* __restrict__ A0,
                                                 const float* __restrict__ A1,
                                                 float* __restrict__ o0,
                                                 float* __restrict__ o1) {
    __shared__ float As[NSTAGE * STG];
    __shared__ float Bs[NSTAGE * STG];
    const float* A = blockIdx.z ? A1 : A0;
    const float* Wt = g_wr + ((size_t)(4 + blockIdx.z) << 20);
    float* C = blockIdx.z ? o1 : o0;
    float alpha = blockIdx.z ? 1.0f : 0.3f;
    gemm_body(A, Wt, C, alpha, blockIdx.x, blockIdx.y, As, Bs);
}

// ---------------- gate: weights cached in smem, 32 rows/block ----------------
#define GATE_DSMEM (Hc * Dc * 4)   // 64 KB
__global__ __launch_bounds__(512) void gate_k(const float* __restrict__ wg,
                                              const float* __restrict__ bg) {
    extern __shared__ float wgs[];
    __shared__ float hs[32][17];
    int tid = threadIdx.x;
    int w = tid >> 5;
    int lane = tid & 31;
    // load 16x1024 weights into smem
    for (int i = tid; i < Hc * Dc / 4; i += 512)
        ((float4*)wgs)[i] = ((const float4*)wg)[i];
    __syncthreads();

    float bias = bg[w];
    int row0 = blockIdx.x * 32;
    const ulonglong2* ws2 = (const ulonglong2*)(wgs + w * Dc);
    for (int rl = 0; rl < 32; rl++) {
        const ulonglong2* xr2 = (const ulonglong2*)(g_xn + (size_t)(row0 + rl) * Dc);
        u64 sp = 0ull;
#pragma unroll
        for (int it = 0; it < 8; it++) {
            ulonglong2 xv = xr2[lane + 32 * it];
            ulonglong2 wv = ws2[lane + 32 * it];
            sp = fma2(xv.x, wv.x, sp);
            sp = fma2(xv.y, wv.y, sp);
        }
        float slo, shi;
        unpack2(sp, slo, shi);
        float s = slo + shi;
#pragma unroll
        for (int o = 16; o > 0; o >>= 1) s += __shfl_xor_sync(0xffffffffu, s, o);
        if (lane == 0) hs[rl][w] = 1.f / (1.f + __expf(-(s + bias)));
    }
    __syncthreads();
    if (tid < 32) {
        float m = 0.f;
#pragma unroll
        for (int h = 0; h < 16; h++) m += hs[tid][h];
        g_gate[row0 + tid] = m * (1.f / 16.f);
    }
}

// ---------------- RoPE (in place; q and k in one launch) ----------------
__global__ __launch_bounds__(256) void rope_k(float* __restrict__ pq,
                                              float* __restrict__ pk) {
    float* p = blockIdx.y ? pk : pq;
    int gid = blockIdx.x * 256 + threadIdx.x;
    int row = gid >> 9;
    int rem = gid & 511;
    int h = rem >> 5;
    int i = rem & 31;
    int t = row & (Tc - 1);
    int base = row * Dc + h * 64 + i;
    float u1 = p[base];
    float u2 = p[base + 32];
    float fr = exp2f(-(float)i * 0.41524100184f);
    float ang = (float)t * fr;
    float cc, ss;
    __sincosf(ang, &ss, &cc);
    p[base] = u1 * cc - u2 * ss;
    p[base + 32] = u2 * cc + u1 * ss;
}

// ---------------- sliding-window attention (f32x2 packed math) --------------
#define ATTN_SMEM ((64 * 68 * 2 + 128 * 66) * 4)
__global__ __launch_bounds__(128) void attn_k() {
    extern __shared__ float sm[];
    float* ks = sm;                // 64 x 68
    float* vs = sm + 64 * 68;      // 64 x 68
    float* ps = sm + 2 * 64 * 68;  // 128 x 66 (q staging, then scores)
    int tid = threadIdx.x;
    int q0 = blockIdx.x * 128;
    int h = blockIdx.y;
    int b = blockIdx.z;
    int tq = q0 + tid;

    const float* qbase = g_q + (size_t)(b * Tc + q0) * Dc + h * 64;
#pragma unroll 4
    for (int it = 0; it < 64; it++) {
        int id = it * 128 + tid;
        int r = id >> 6, d = id & 63;
        ps[r * 66 + d] = qbase[(size_t)r * Dc + d];
    }
    __syncthreads();
    u64 qp[32];
    {
        const u64* q2 = (const u64*)(ps + tid * 66);
#pragma unroll
        for (int i = 0; i < 32; i++) qp[i] = q2[i];
    }
    __syncthreads();

    float m = -1e30f, l = 0.f;
    u64 accp[32];
#pragma unroll
    for (int i = 0; i < 32; i++) accp[i] = 0ull;

    int s_start = q0 - Wc;
    if (s_start < 0) s_start = 0;
    for (int s0 = s_start; s0 < q0 + 128; s0 += 64) {
        const float* kb = g_k + (size_t)(b * Tc + s0) * Dc + h * 64;
        const float* vb = g_v + (size_t)(b * Tc + s0) * Dc + h * 64;
#pragma unroll 4
        for (int it = 0; it < 32; it++) {
            int id = it * 128 + tid;
            int r = id >> 6, d = id & 63;
            ks[r * 68 + d] = kb[(size_t)r * Dc + d];
            vs[r * 68 + d] = vb[(size_t)r * Dc + d];
        }
        __syncthreads();

        float tmax = -1e30f;
        for (int j = 0; j < 64; j++) {
            const u64* k2 = (const u64*)(ks + j * 68);
            u64 sp = 0ull;
#pragma unroll
            for (int i = 0; i < 32; i++) sp = fma2(qp[i], k2[i], sp);
            float slo, shi;
            unpack2(sp, slo, shi);
            float s = (slo + shi) * 0.125f;
            int sg = s0 + j;
            if (sg > tq || sg < tq - Wc) s = -1e30f;
            ps[tid * 66 + j] = s;
            tmax = fmaxf(tmax, s);
        }
        float mnew = fmaxf(m, tmax);
        float corr = __expf(m - mnew);
        l *= corr;
        u64 corrp = pack2(corr, corr);
#pragma unroll
        for (int i = 0; i < 32; i++) accp[i] = mul2(accp[i], corrp);
        for (int j = 0; j < 64; j++) {
            float sv = ps[tid * 66 + j];
            float p = (sv > -1e29f) ? __expf(sv - mnew) : 0.f;
            l += p;
            u64 pp = pack2(p, p);
            const u64* v2 = (const u64*)(vs + j * 68);
#pragma unroll
            for (int i = 0; i < 32; i++) accp[i] = fma2(pp, v2[i], accp[i]);
        }
        m = mnew;
        __syncthreads();
    }
    float inv = 1.f / l;
    float* ob = g_local + (size_t)(b * Tc + tq) * Dc + h * 64;
#pragma unroll
    for (int i = 0; i < 32; i++) {
        float lo, hi;
        unpack2(accp[i], lo, hi);
        ob[2 * i] = tf32r(lo * inv);
        ob[2 * i + 1] = tf32r(hi * inv);
    }
}

// ---------------- retrieval (output tf32-rounded) ----------------
__global__ __launch_bounds__(256) void retr_k(const float* __restrict__ state,
                                              const int* __restrict__ ids,
                                              const float* __restrict__ bank) {
    __shared__ float st[64 * 64];
    __shared__ float qs[4][64];
    int tc = blockIdx.x;
    int h = blockIdx.y;
    int b = blockIdx.z;
    int tid = threadIdx.x;
    const float* sb = state + (size_t)((b * Hc + h) * 64) * 64;
    for (int i = tid; i < 4096; i += 256) st[i] = sb[i];
    __syncthreads();
    int tloc = tid >> 6;
    int kk = tid & 63;
    for (int t0 = tc * 128; t0 < tc * 128 + 128; t0 += 4) {
        int t = t0 + tloc;
        int ii = ids[b * Tc + t] - CUE_C;
        float val;
        if (ii >= 0 && ii < BANK_C)
            val = bank[(size_t)(h * BANK_C + ii) * 64 + kk];
        else
            val = g_qg[(size_t)(b * Tc + t) * Dc + h * 64 + kk];
        qs[tloc][kk] = val;
        __syncthreads();
        float sum = 0.f;
#pragma unroll
        for (int k2 = 0; k2 < 64; k2++) sum += st[k2 * 64 + kk] * qs[tloc][k2];
        g_ret[(size_t)(b * Tc + t) * Dc + h * 64 + kk] = tf32r(sum);
        __syncthreads();
    }
}

// ---------------- final combine ----------------
__global__ __launch_bounds__(256) void combine_k(const float* __restrict__ x,
                                                 float* __restrict__ out) {
    int idx = blockIdx.x * 256 + threadIdx.x;
    int row = idx >> 8;
    float g = g_gate[row];
    float4 xv = ((const float4*)x)[idx];
    float4 lv = ((const float4*)g_localO)[idx];
    float4 rv = ((const float4*)g_ro)[idx];
    float4 o;
    o.x = xv.x + lv.x + g * rv.x;
    o.y = xv.y + lv.y + g * rv.y;
    o.z = xv.z + lv.z + g * rv.z;
    o.w = xv.w + lv.w + g * rv.w;
    ((float4*)out)[idx] = o;
}

// ---------------- launch ----------------
extern "C" void kernel_launch(void* const* d_in, const int* in_sizes, int n_in,
                              void* d_out, int out_size) {
    const float* x = (const float*)d_in[0];
    const float* gdn = (const float*)d_in[1];
    const int* ids = (const int*)d_in[2];
    const float* bank = (const float*)d_in[3];
    const float* normw = (const float*)d_in[4];
    const float* wq = (const float*)d_in[5];
    const float* wk = (const float*)d_in[6];
    const float* wv = (const float*)d_in[7];
    const float* wo = (const float*)d_in[8];
    const float* wgq = (const float*)d_in[9];
    const float* wro = (const float*)d_in[10];
    const float* wgate = (const float*)d_in[11];
    const float* bgate = (const float*)d_in[12];
    float* out = (float*)d_out;

    float *xn, *q, *k, *v, *qg, *loc, *locO, *ret, *ro;
    cudaGetSymbolAddress((void**)&xn, g_xn);
    cudaGetSymbolAddress((void**)&q, g_q);
    cudaGetSymbolAddress((void**)&k, g_k);
    cudaGetSymbolAddress((void**)&v, g_v);
    cudaGetSymbolAddress((void**)&qg, g_qg);
    cudaGetSymbolAddress((void**)&loc, g_local);
    cudaGetSymbolAddress((void**)&locO, g_localO);
    cudaGetSymbolAddress((void**)&ret, g_ret);
    cudaGetSymbolAddress((void**)&ro, g_ro);

    cudaFuncSetAttribute(attn_k, cudaFuncAttributeMaxDynamicSharedMemorySize,
                         ATTN_SMEM);
    cudaFuncSetAttribute(gate_k, cudaFuncAttributeMaxDynamicSharedMemorySize,
                         GATE_DSMEM);

    // round weights: order matches g_wr slots 0..5 (wq,wk,wv,wgq,wo,wro)
    roundw_k<<<6144, 256>>>(wq, wk, wv, wgq, wo, wro);

    rmsnorm_k<<<MROWS, 256>>>(x, normw);

    dim3 gg4(Dc / 128, MROWS / 128, 4);  // 1024 blocks
    tgemm4<<<gg4, 256>>>(xn, q, k, v, qg);

    gate_k<<<MROWS / 32, 512, GATE_DSMEM>>>(wgate, bgate);

    rope_k<<<dim3((MROWS * Hc * 32) / 256, 2), 256>>>(q, k);

    retr_k<<<dim3(Tc / 128, Hc, Bc), 256>>>(gdn, ids, bank);

    attn_k<<<dim3(Tc / 128, Hc, Bc), 128, ATTN_SMEM>>>();

    dim3 gg2(Dc / 128, MROWS / 128, 2);  // 512 blocks
    tgemm2<<<gg2, 256>>>(loc, ret, locO, ro);

    combine_k<<<(MROWS * Dc / 4) / 256, 256>>>(x, out);
}

// round 15
// speedup vs baseline: 2.2779x; 1.0005x over previous
#include <cuda_runtime.h>
#include <math.h>
#include <stdint.h>

// Problem dims
#define Bc 2
#define Tc 2048
#define Dc 1024
#define Hc 16
#define Kc 64
#define Vc 64
#define Wc 256
#define MROWS (Bc * Tc)          // 4096
#define CUE_C 50250
#define BANK_C 64

typedef unsigned long long u64;

// ---------------- scratch (device globals; no allocs allowed) ----------------
__device__ float g_xn[MROWS * Dc];
__device__ float g_q[MROWS * Dc];
__device__ float g_k[MROWS * Dc];
__device__ float g_v[MROWS * Dc];
__device__ float g_qg[MROWS * Dc];
__device__ float g_local[MROWS * Dc];
__device__ float g_localO[MROWS * Dc];
__device__ float g_ret[MROWS * Dc];
__device__ float g_ro[MROWS * Dc];
__device__ float g_gate[MROWS];
__device__ float g_wr[6 * Dc * Dc];   // tf32-rounded weights

// ---------------- helpers ----------------
__device__ __forceinline__ float tf32r(float f) {
    uint32_t u;
    asm("cvt.rna.tf32.f32 %0, %1;" : "=r"(u) : "f"(f));
    return __uint_as_float(u);
}

__device__ __forceinline__ u64 pack2(float lo, float hi) {
    u64 r;
    asm("mov.b64 %0, {%1, %2};" : "=l"(r) : "f"(lo), "f"(hi));
    return r;
}
__device__ __forceinline__ void unpack2(u64 v, float& lo, float& hi) {
    asm("mov.b64 {%0, %1}, %2;" : "=f"(lo), "=f"(hi) : "l"(v));
}
__device__ __forceinline__ u64 fma2(u64 a, u64 b, u64 c) {
    u64 d;
    asm("fma.rn.f32x2 %0, %1, %2, %3;" : "=l"(d) : "l"(a), "l"(b), "l"(c));
    return d;
}
__device__ __forceinline__ u64 mul2(u64 a, u64 b) {
    u64 d;
    asm("mul.rn.f32x2 %0, %1, %2;" : "=l"(d) : "l"(a), "l"(b));
    return d;
}

__device__ __forceinline__ void mma_tf32(float& d0, float& d1, float& d2, float& d3,
                                         uint32_t a0, uint32_t a1, uint32_t a2, uint32_t a3,
                                         uint32_t b0, uint32_t b1) {
    asm volatile(
        "mma.sync.aligned.m16n8k8.row.col.f32.tf32.tf32.f32 "
        "{%0,%1,%2,%3}, {%4,%5,%6,%7}, {%8,%9}, {%0,%1,%2,%3};\n"
        : "+f"(d0), "+f"(d1), "+f"(d2), "+f"(d3)
        : "r"(a0), "r"(a1), "r"(a2), "r"(a3), "r"(b0), "r"(b1));
}

__device__ __forceinline__ void cpa16(void* smem, const void* gmem) {
    uint32_t s = (uint32_t)__cvta_generic_to_shared(smem);
    asm volatile("cp.async.cg.shared.global [%0], [%1], 16;\n" ::"r"(s), "l"(gmem));
}
#define CP_COMMIT() asm volatile("cp.async.commit_group;\n" ::: "memory")
#define CP_WAIT2() asm volatile("cp.async.wait_group 2;\n" ::: "memory")

// ---------------- weight rounding (once per call; memory-bound) -------------
__global__ __launch_bounds__(256) void roundw_k(const float* __restrict__ w0,
                                                const float* __restrict__ w1,
                                                const float* __restrict__ w2,
                                                const float* __restrict__ w3,
                                                const float* __restrict__ w4,
                                                const float* __restrict__ w5) {
    int gid = blockIdx.x * 256 + threadIdx.x;
    int sel = gid >> 18;
    int off = gid & 262143;
    const float* w;
    switch (sel) {
        case 0: w = w0; break;
        case 1: w = w1; break;
        case 2: w = w2; break;
        case 3: w = w3; break;
        case 4: w = w4; break;
        default: w = w5; break;
    }
    float4 v = ((const float4*)w)[off];
    v.x = tf32r(v.x); v.y = tf32r(v.y); v.z = tf32r(v.z); v.w = tf32r(v.w);
    ((float4*)(g_wr + ((size_t)sel << 20)))[off] = v;
}

// ---------------- RMSNorm (outputs tf32-rounded) ----------------
__global__ __launch_bounds__(256) void rmsnorm_k(const float* __restrict__ x,
                                                 const float* __restrict__ w) {
    int row = blockIdx.x;
    int tid = threadIdx.x;
    const float4* xr = (const float4*)(x + row * Dc);
    float4 vv = xr[tid];
    float s = vv.x * vv.x + vv.y * vv.y + vv.z * vv.z + vv.w * vv.w;
    __shared__ float red[256];
    red[tid] = s;
    __syncthreads();
    for (int o = 128; o > 0; o >>= 1) {
        if (tid < o) red[tid] += red[tid + o];
        __syncthreads();
    }
    float inv = rsqrtf(red[0] * (1.0f / Dc) + 1e-6f);
    float4 wv = ((const float4*)w)[tid];
    float4 o;
    o.x = tf32r(vv.x * inv * wv.x);
    o.y = tf32r(vv.y * inv * wv.y);
    o.z = tf32r(vv.z * inv * wv.z);
    o.w = tf32r(vv.w * inv * wv.w);
    ((float4*)(g_xn + row * Dc))[tid] = o;
}

// ---------------- tf32 tensor-core GEMM, 4-stage cp.async pipeline ----------
#define PADW 20
#define STG (128 * PADW)
#define NSTAGE 4

__device__ __forceinline__ void gemm_body(const float* __restrict__ A,
                                          const float* __restrict__ Wt,
                                          float* __restrict__ C, float alpha,
                                          int bx, int by,
                                          float* As, float* Bs) {
    int tid = threadIdx.x;
    int lane = tid & 31;
    int wid = tid >> 5;
    int wm = (wid >> 2) * 64;
    int wn = (wid & 3) * 32;
    int r = lane >> 2;
    int c = lane & 3;
    int m0 = by * 128;
    int n0 = bx * 128;

    int row0 = tid >> 2;
    int kq = (tid & 3) * 4;
    const float* Ab0 = A + (size_t)(m0 + row0) * Dc + kq;
    const float* Ab1 = A + (size_t)(m0 + row0 + 64) * Dc + kq;
    const float* Bb0 = Wt + (size_t)(n0 + row0) * Dc + kq;
    const float* Bb1 = Wt + (size_t)(n0 + row0 + 64) * Dc + kq;

    float acc[4][4][4];
#pragma unroll
    for (int i = 0; i < 4; i++)
#pragma unroll
        for (int j = 0; j < 4; j++)
#pragma unroll
            for (int e = 0; e < 4; e++) acc[i][j][e] = 0.f;

    const int nIter = Dc / 16;

#define FILL(st, koff)                                          \
    do {                                                        \
        float* as_ = As + (st) * STG;                           \
        float* bs_ = Bs + (st) * STG;                           \
        cpa16(as_ + row0 * PADW + kq, Ab0 + (koff));            \
        cpa16(as_ + (row0 + 64) * PADW + kq, Ab1 + (koff));     \
        cpa16(bs_ + row0 * PADW + kq, Bb0 + (koff));            \
        cpa16(bs_ + (row0 + 64) * PADW + kq, Bb1 + (koff));     \
    } while (0)

    FILL(0, 0); CP_COMMIT();
    FILL(1, 16); CP_COMMIT();
    FILL(2, 32); CP_COMMIT();

    for (int it = 0; it < nIter; it++) {
        CP_WAIT2();
        __syncthreads();

        if (it + 3 < nIter) FILL((it + 3) & 3, (it + 3) * 16);
        CP_COMMIT();

        const uint32_t* as = (const uint32_t*)(As + (it & 3) * STG);
        const uint32_t* bs = (const uint32_t*)(Bs + (it & 3) * STG);
#pragma unroll
        for (int ks = 0; ks < 16; ks += 8) {
            uint32_t af[4][4], bf[4][2];
#pragma unroll
            for (int mt = 0; mt < 4; mt++) {
                const uint32_t* p = as + (wm + mt * 16 + r) * PADW + ks + c;
                af[mt][0] = p[0];
                af[mt][1] = p[8 * PADW];
                af[mt][2] = p[4];
                af[mt][3] = p[8 * PADW + 4];
            }
#pragma unroll
            for (int nt = 0; nt < 4; nt++) {
                const uint32_t* p = bs + (wn + nt * 8 + r) * PADW + ks + c;
                bf[nt][0] = p[0];
                bf[nt][1] = p[4];
            }
#pragma unroll
            for (int mt = 0; mt < 4; mt++)
#pragma unroll
                for (int nt = 0; nt < 4; nt++)
                    mma_tf32(acc[mt][nt][0], acc[mt][nt][1], acc[mt][nt][2], acc[mt][nt][3],
                             af[mt][0], af[mt][1], af[mt][2], af[mt][3],
                             bf[nt][0], bf[nt][1]);
        }
        __syncthreads();
    }
#undef FILL

#pragma unroll
    for (int mt = 0; mt < 4; mt++) {
#pragma unroll
        for (int nt = 0; nt < 4; nt++) {
            float* p = C + (size_t)(m0 + wm + mt * 16 + r) * Dc + n0 + wn + nt * 8 + 2 * c;
            float2 v0, v1;
            v0.x = alpha * acc[mt][nt][0];
            v0.y = alpha * acc[mt][nt][1];
            v1.x = alpha * acc[mt][nt][2];
            v1.y = alpha * acc[mt][nt][3];
            *(float2*)p = v0;
            *(float2*)(p + 8 * Dc) = v1;
        }
    }
}

// batched 4-way GEMM (q, k, v, q_g share the A matrix g_xn)
__global__ __launch_bounds__(256, 2) void tgemm4(const float* __restrict__ A,
                                                 float* __restrict__ o0,
                                                 float* __restrict__ o1,
                                                 float* __restrict__ o2,
                                                 float* __restrict__ o3) {
    __shared__ float As[NSTAGE * STG];
    __shared__ float Bs[NSTAGE * STG];
    const float* Wt = g_wr + ((size_t)blockIdx.z << 20);
    float* C;
    switch (blockIdx.z) {
        case 0: C = o0; break;
        case 1: C = o1; break;
        case 2: C = o2; break;
        default: C = o3; break;
    }
    gemm_body(A, Wt, C, 1.0f, blockIdx.x, blockIdx.y, As, Bs);
}

// batched 2-way GEMM for the tail: slot0 loc@wo (alpha .3), slot1 ret@wro
__global__ __launch_bounds__(256, 2) void tgemm2(const float* __restrict__ A0,
                                                 const float* __restrict__ A1,
                                                 float* __restrict__ o0,
                                                 float* __restrict__ o1) {
    __shared__ float As[NSTAGE * STG];
    __shared__ float Bs[NSTAGE * STG];
    const float* A = blockIdx.z ? A1 : A0;
    const float* Wt = g_wr + ((size_t)(4 + blockIdx.z) << 20);
    float* C = blockIdx.z ? o1 : o0;
    float alpha = blockIdx.z ? 1.0f : 0.3f;
    gemm_body(A, Wt, C, alpha, blockIdx.x, blockIdx.y, As, Bs);
}

// ---------------- gate v3: 8 rows/block, weights in registers per warp ------
__global__ __launch_bounds__(256) void gate_k(const float* __restrict__ wg,
                                              const float* __restrict__ bg) {
    __shared__ float hs[8][17];
    int tid = threadIdx.x;
    int lane = tid & 31;
    int w = tid >> 5;              // warp 0..7
    int r0 = blockIdx.x * 8;
#pragma unroll
    for (int hh = 0; hh < 2; hh++) {
        int h = w * 2 + hh;
        u64 wreg[16];
        const u64* wp = (const u64*)(wg + h * Dc) + lane;
#pragma unroll
        for (int i = 0; i < 16; i++) wreg[i] = wp[32 * i];
        float bias = bg[h];
        for (int r = 0; r < 8; r++) {
            const u64* xp = (const u64*)(g_xn + (size_t)(r0 + r) * Dc) + lane;
            u64 sp = 0ull;
#pragma unroll
            for (int i = 0; i < 16; i++) sp = fma2(xp[32 * i], wreg[i], sp);
            float lo, hi;
            unpack2(sp, lo, hi);
            float s = lo + hi;
#pragma unroll
            for (int o = 16; o > 0; o >>= 1)
                s += __shfl_xor_sync(0xffffffffu, s, o);
            if (lane == 0) hs[r][h] = 1.f / (1.f + __expf(-(s + bias)));
        }
    }
    __syncthreads();
    if (tid < 8) {
        float m = 0.f;
#pragma unroll
        for (int h = 0; h < 16; h++) m += hs[tid][h];
        g_gate[r0 + tid] = m * (1.f / 16.f);
    }
}

// ---------------- RoPE (in place; q and k in one launch) ----------------
__global__ __launch_bounds__(256) void rope_k(float* __restrict__ pq,
                                              float* __restrict__ pk) {
    float* p = blockIdx.y ? pk : pq;
    int gid = blockIdx.x * 256 + threadIdx.x;
    int row = gid >> 9;
    int rem = gid & 511;
    int h = rem >> 5;
    int i = rem & 31;
    int t = row & (Tc - 1);
    int base = row * Dc + h * 64 + i;
    float u1 = p[base];
    float u2 = p[base + 32];
    float fr = exp2f(-(float)i * 0.41524100184f);
    float ang = (float)t * fr;
    float cc, ss;
    __sincosf(ang, &ss, &cc);
    p[base] = u1 * cc - u2 * ss;
    p[base + 32] = u2 * cc + u1 * ss;
}

// ---------------- sliding-window attention: QK^T on tensor cores -----------
// 256 threads (8 warps). S = QK^T via tf32 MMA into smem; softmax + PV scalar
// f32x2 with 2 threads per query row (32 dims each).
#define APAD 68
#define PPAD 65
#define ATTN_SMEM ((128 * APAD + 2 * 64 * APAD + 128 * PPAD) * 4)
__global__ __launch_bounds__(256) void attn_k() {
    extern __shared__ float sm[];
    float* qs = sm;                        // 128 x APAD (tf32)
    float* ks = qs + 128 * APAD;           // 64 x APAD (tf32)
    float* vs = ks + 64 * APAD;            // 64 x APAD (f32)
    float* ps = vs + 64 * APAD;            // 128 x PPAD (scores)
    int tid = threadIdx.x;
    int lane = tid & 31;
    int wid = tid >> 5;
    int q0 = blockIdx.x * 128;
    int h = blockIdx.y;
    int b = blockIdx.z;

    // load Q tile (tf32-rounded)
    const float* qbase = g_q + (size_t)(b * Tc + q0) * Dc + h * 64;
#pragma unroll 4
    for (int it = 0; it < 32; it++) {
        int id = it * 256 + tid;
        int r = id >> 6, d = id & 63;
        qs[r * APAD + d] = tf32r(qbase[(size_t)r * Dc + d]);
    }

    // per-thread softmax/PV state: 2 threads per row
    int row = tid & 127;
    int half = tid >> 7;
    int tq = q0 + row;
    float m = -1e30f, l = 0.f;
    u64 accp[16];
#pragma unroll
    for (int i = 0; i < 16; i++) accp[i] = 0ull;

    int wm = wid * 16;
    int r4 = lane >> 2;
    int c4 = lane & 3;

    int s_start = q0 - Wc;
    if (s_start < 0) s_start = 0;
    __syncthreads();

    for (int s0 = s_start; s0 < q0 + 128; s0 += 64) {
        // load K (tf32) + V tiles
        const float* kb = g_k + (size_t)(b * Tc + s0) * Dc + h * 64;
        const float* vb = g_v + (size_t)(b * Tc + s0) * Dc + h * 64;
#pragma unroll 4
        for (int it = 0; it < 16; it++) {
            int id = it * 256 + tid;
            int r = id >> 6, d = id & 63;
            ks[r * APAD + d] = tf32r(kb[(size_t)r * Dc + d]);
            vs[r * APAD + d] = vb[(size_t)r * Dc + d];
        }
        __syncthreads();

        // S tile via MMA: warp rows wm..wm+15, cols 0..63
        float acc[8][4];
#pragma unroll
        for (int nt = 0; nt < 8; nt++)
#pragma unroll
            for (int e = 0; e < 4; e++) acc[nt][e] = 0.f;

#pragma unroll
        for (int ks8 = 0; ks8 < 64; ks8 += 8) {
            const uint32_t* ap = (const uint32_t*)qs + (wm + r4) * APAD + ks8 + c4;
            uint32_t a0 = ap[0];
            uint32_t a1 = ap[8 * APAD];
            uint32_t a2 = ap[4];
            uint32_t a3 = ap[8 * APAD + 4];
#pragma unroll
            for (int nt = 0; nt < 8; nt++) {
                const uint32_t* bp = (const uint32_t*)ks + (nt * 8 + r4) * APAD + ks8 + c4;
                mma_tf32(acc[nt][0], acc[nt][1], acc[nt][2], acc[nt][3],
                         a0, a1, a2, a3, bp[0], bp[4]);
            }
        }
        // write scores (scaled) to ps
#pragma unroll
        for (int nt = 0; nt < 8; nt++) {
            int col = nt * 8 + 2 * c4;
            float* p0 = ps + (wm + r4) * PPAD + col;
            float* p1 = ps + (wm + r4 + 8) * PPAD + col;
            p0[0] = acc[nt][0] * 0.125f;
            p0[1] = acc[nt][1] * 0.125f;
            p1[0] = acc[nt][2] * 0.125f;
            p1[1] = acc[nt][3] * 0.125f;
        }
        __syncthreads();

        // softmax + PV (per-thread: row, half)
        const float* prow = ps + row * PPAD;
        int jhi = tq - s0;            // j <= jhi
        int jlo = jhi - Wc;           // j >= jlo
        float tmax = -1e30f;
        float sv[64];
#pragma unroll
        for (int j = 0; j < 64; j++) {
            float s = prow[j];
            if (j > jhi || j < jlo) s = -1e30f;
            sv[j] = s;
            tmax = fmaxf(tmax, s);
        }
        float mnew = fmaxf(m, tmax);
        float corr = __expf(m - mnew);
        l *= corr;
        u64 corrp = pack2(corr, corr);
#pragma unroll
        for (int i = 0; i < 16; i++) accp[i] = mul2(accp[i], corrp);
#pragma unroll
        for (int j = 0; j < 64; j++) {
            float p = (sv[j] > -1e29f) ? __expf(sv[j] - mnew) : 0.f;
            l += p;
            u64 pp = pack2(p, p);
            const u64* v2 = (const u64*)(vs + j * APAD + half * 32);
#pragma unroll
            for (int i = 0; i < 16; i++) accp[i] = fma2(pp, v2[i], accp[i]);
        }
        m = mnew;
        __syncthreads();
    }

    float inv = 1.f / l;
    float* ob = g_local + (size_t)(b * Tc + tq) * Dc + h * 64 + half * 32;
#pragma unroll
    for (int i = 0; i < 16; i++) {
        float lo, hi;
        unpack2(accp[i], lo, hi);
        ob[2 * i] = tf32r(lo * inv);
        ob[2 * i + 1] = tf32r(hi * inv);
    }
}

// ---------------- retrieval (output tf32-rounded) ----------------
__global__ __launch_bounds__(256) void retr_k(const float* __restrict__ state,
                                              const int* __restrict__ ids,
                                              const float* __restrict__ bank) {
    __shared__ float st[64 * 64];
    __shared__ float qs[4][64];
    int tc = blockIdx.x;
    int h = blockIdx.y;
    int b = blockIdx.z;
    int tid = threadIdx.x;
    const float* sb = state + (size_t)((b * Hc + h) * 64) * 64;
    for (int i = tid; i < 4096; i += 256) st[i] = sb[i];
    __syncthreads();
    int tloc = tid >> 6;
    int kk = tid & 63;
    for (int t0 = tc * 128; t0 < tc * 128 + 128; t0 += 4) {
        int t = t0 + tloc;
        int ii = ids[b * Tc + t] - CUE_C;
        float val;
        if (ii >= 0 && ii < BANK_C)
            val = bank[(size_t)(h * BANK_C + ii) * 64 + kk];
        else
            val = g_qg[(size_t)(b * Tc + t) * Dc + h * 64 + kk];
        qs[tloc][kk] = val;
        __syncthreads();
        float sum = 0.f;
#pragma unroll
        for (int k2 = 0; k2 < 64; k2++) sum += st[k2 * 64 + kk] * qs[tloc][k2];
        g_ret[(size_t)(b * Tc + t) * Dc + h * 64 + kk] = tf32r(sum);
        __syncthreads();
    }
}

// ---------------- final combine ----------------
__global__ __launch_bounds__(256) void combine_k(const float* __restrict__ x,
                                                 float* __restrict__ out) {
    int idx = blockIdx.x * 256 + threadIdx.x;
    int row = idx >> 8;
    float g = g_gate[row];
    float4 xv = ((const float4*)x)[idx];
    float4 lv = ((const float4*)g_localO)[idx];
    float4 rv = ((const float4*)g_ro)[idx];
    float4 o;
    o.x = xv.x + lv.x + g * rv.x;
    o.y = xv.y + lv.y + g * rv.y;
    o.z = xv.z + lv.z + g * rv.z;
    o.w = xv.w + lv.w + g * rv.w;
    ((float4*)out)[idx] = o;
}

// ---------------- launch ----------------
extern "C" void kernel_launch(void* const* d_in, const int* in_sizes, int n_in,
                              void* d_out, int out_size) {
    const float* x = (const float*)d_in[0];
    const float* gdn = (const float*)d_in[1];
    const int* ids = (const int*)d_in[2];
    const float* bank = (const float*)d_in[3];
    const float* normw = (const float*)d_in[4];
    const float* wq = (const float*)d_in[5];
    const float* wk = (const float*)d_in[6];
    const float* wv = (const float*)d_in[7];
    const float* wo = (const float*)d_in[8];
    const float* wgq = (const float*)d_in[9];
    const float* wro = (const float*)d_in[10];
    const float* wgate = (const float*)d_in[11];
    const float* bgate = (const float*)d_in[12];
    float* out = (float*)d_out;

    float *xn, *q, *k, *v, *qg, *loc, *locO, *ret, *ro;
    cudaGetSymbolAddress((void**)&xn, g_xn);
    cudaGetSymbolAddress((void**)&q, g_q);
    cudaGetSymbolAddress((void**)&k, g_k);
    cudaGetSymbolAddress((void**)&v, g_v);
    cudaGetSymbolAddress((void**)&qg, g_qg);
    cudaGetSymbolAddress((void**)&loc, g_local);
    cudaGetSymbolAddress((void**)&locO, g_localO);
    cudaGetSymbolAddress((void**)&ret, g_ret);
    cudaGetSymbolAddress((void**)&ro, g_ro);

    cudaFuncSetAttribute(attn_k, cudaFuncAttributeMaxDynamicSharedMemorySize,
                         ATTN_SMEM);

    // round weights: order matches g_wr slots 0..5 (wq,wk,wv,wgq,wo,wro)
    roundw_k<<<6144, 256>>>(wq, wk, wv, wgq, wo, wro);

    rmsnorm_k<<<MROWS, 256>>>(x, normw);

    dim3 gg4(Dc / 128, MROWS / 128, 4);  // 1024 blocks
    tgemm4<<<gg4, 256>>>(xn, q, k, v, qg);

    gate_k<<<MROWS / 8, 256>>>(wgate, bgate);

    rope_k<<<dim3((MROWS * Hc * 32) / 256, 2), 256>>>(q, k);

    retr_k<<<dim3(Tc / 128, Hc, Bc), 256>>>(gdn, ids, bank);

    attn_k<<<dim3(Tc / 128, Hc, Bc), 256, ATTN_SMEM>>>();

    dim3 gg2(Dc / 128, MROWS / 128, 2);  // 512 blocks
    tgemm2<<<gg2, 256>>>(loc, ret, locO, ro);

    combine_k<<<(MROWS * Dc / 4) / 256, 256>>>(x, out);
}

// round 17
// speedup vs baseline: 2.4363x; 1.0695x over previous
#include <cuda_runtime.h>
#include <math.h>
#include <stdint.h>

// Problem dims
#define Bc 2
#define Tc 2048
#define Dc 1024
#define Hc 16
#define Kc 64
#define Vc 64
#define Wc 256
#define MROWS (Bc * Tc)          // 4096
#define CUE_C 50250
#define BANK_C 64

typedef unsigned long long u64;

// ---------------- scratch (device globals; no allocs allowed) ----------------
__device__ float g_xn[MROWS * Dc];
__device__ float g_q[MROWS * Dc];
__device__ float g_k[MROWS * Dc];
__device__ float g_v[MROWS * Dc];
__device__ float g_qg[MROWS * Dc];
__device__ float g_local[MROWS * Dc];
__device__ float g_localO[MROWS * Dc];
__device__ float g_ret[MROWS * Dc];
__device__ float g_ro[MROWS * Dc];
__device__ float g_gate[MROWS];
__device__ float g_wr[6 * Dc * Dc];   // tf32-rounded weights

// ---------------- helpers ----------------
__device__ __forceinline__ float tf32r(float f) {
    uint32_t u;
    asm("cvt.rna.tf32.f32 %0, %1;" : "=r"(u) : "f"(f));
    return __uint_as_float(u);
}
__device__ __forceinline__ u64 pack2(float lo, float hi) {
    u64 r;
    asm("mov.b64 %0, {%1, %2};" : "=l"(r) : "f"(lo), "f"(hi));
    return r;
}
__device__ __forceinline__ void unpack2(u64 v, float& lo, float& hi) {
    asm("mov.b64 {%0, %1}, %2;" : "=f"(lo), "=f"(hi) : "l"(v));
}
__device__ __forceinline__ u64 fma2(u64 a, u64 b, u64 c) {
    u64 d;
    asm("fma.rn.f32x2 %0, %1, %2, %3;" : "=l"(d) : "l"(a), "l"(b), "l"(c));
    return d;
}
__device__ __forceinline__ u64 mul2(u64 a, u64 b) {
    u64 d;
    asm("mul.rn.f32x2 %0, %1, %2;" : "=l"(d) : "l"(a), "l"(b));
    return d;
}
__device__ __forceinline__ void mma_tf32(float& d0, float& d1, float& d2, float& d3,
                                         uint32_t a0, uint32_t a1, uint32_t a2, uint32_t a3,
                                         uint32_t b0, uint32_t b1) {
    asm volatile(
        "mma.sync.aligned.m16n8k8.row.col.f32.tf32.tf32.f32 "
        "{%0,%1,%2,%3}, {%4,%5,%6,%7}, {%8,%9}, {%0,%1,%2,%3};\n"
        : "+f"(d0), "+f"(d1), "+f"(d2), "+f"(d3)
        : "r"(a0), "r"(a1), "r"(a2), "r"(a3), "r"(b0), "r"(b1));
}
__device__ __forceinline__ uint32_t smem_u32(const void* p) {
    uint32_t a;
    asm("{ .reg .u64 t; cvta.to.shared.u64 t, %1; cvt.u32.u64 %0, t; }"
        : "=r"(a) : "l"(p));
    return a;
}
__device__ __forceinline__ void ldsm_x4(uint32_t* r, uint32_t a) {
    asm volatile("ldmatrix.sync.aligned.m8n8.x4.shared.b16 {%0,%1,%2,%3}, [%4];"
                 : "=r"(r[0]), "=r"(r[1]), "=r"(r[2]), "=r"(r[3]) : "r"(a));
}
__device__ __forceinline__ void ldsm_x2(uint32_t* r, uint32_t a) {
    asm volatile("ldmatrix.sync.aligned.m8n8.x2.shared.b16 {%0,%1}, [%2];"
                 : "=r"(r[0]), "=r"(r[1]) : "r"(a));
}
__device__ __forceinline__ void cpa16(void* smem, const void* gmem) {
    uint32_t s = (uint32_t)__cvta_generic_to_shared(smem);
    asm volatile("cp.async.cg.shared.global [%0], [%1], 16;\n" ::"r"(s), "l"(gmem));
}
#define CP_COMMIT() asm volatile("cp.async.commit_group;\n" ::: "memory")
#define CP_WAIT2() asm volatile("cp.async.wait_group 2;\n" ::: "memory")

// ---------------- weight rounding (once per call; memory-bound) -------------
__global__ __launch_bounds__(256) void roundw_k(const float* __restrict__ w0,
                                                const float* __restrict__ w1,
                                                const float* __restrict__ w2,
                                                const float* __restrict__ w3,
                                                const float* __restrict__ w4,
                                                const float* __restrict__ w5) {
    int gid = blockIdx.x * 256 + threadIdx.x;
    int sel = gid >> 18;
    int off = gid & 262143;
    const float* w;
    switch (sel) {
        case 0: w = w0; break;
        case 1: w = w1; break;
        case 2: w = w2; break;
        case 3: w = w3; break;
        case 4: w = w4; break;
        default: w = w5; break;
    }
    float4 v = ((const float4*)w)[off];
    v.x = tf32r(v.x); v.y = tf32r(v.y); v.z = tf32r(v.z); v.w = tf32r(v.w);
    ((float4*)(g_wr + ((size_t)sel << 20)))[off] = v;
}

// ---------------- RMSNorm (outputs tf32-rounded) ----------------
__global__ __launch_bounds__(256) void rmsnorm_k(const float* __restrict__ x,
                                                 const float* __restrict__ w) {
    int row = blockIdx.x;
    int tid = threadIdx.x;
    const float4* xr = (const float4*)(x + row * Dc);
    float4 vv = xr[tid];
    float s = vv.x * vv.x + vv.y * vv.y + vv.z * vv.z + vv.w * vv.w;
    __shared__ float red[256];
    red[tid] = s;
    __syncthreads();
    for (int o = 128; o > 0; o >>= 1) {
        if (tid < o) red[tid] += red[tid + o];
        __syncthreads();
    }
    float inv = rsqrtf(red[0] * (1.0f / Dc) + 1e-6f);
    float4 wv = ((const float4*)w)[tid];
    float4 o;
    o.x = tf32r(vv.x * inv * wv.x);
    o.y = tf32r(vv.y * inv * wv.y);
    o.z = tf32r(vv.z * inv * wv.z);
    o.w = tf32r(vv.w * inv * wv.w);
    ((float4*)(g_xn + row * Dc))[tid] = o;
}

// ---------------- tf32 tensor-core GEMM, 4-stage cp.async + ldmatrix -------
#define PADW 20
#define STG (128 * PADW)
#define NSTAGE 4

__device__ __forceinline__ void gemm_body(const float* __restrict__ A,
                                          const float* __restrict__ Wt,
                                          float* __restrict__ C, float alpha,
                                          int bx, int by,
                                          float* As, float* Bs) {
    int tid = threadIdx.x;
    int lane = tid & 31;
    int wid = tid >> 5;
    int wm = (wid >> 2) * 64;
    int wn = (wid & 3) * 32;
    int r = lane >> 2;
    int c = lane & 3;
    int m0 = by * 128;
    int n0 = bx * 128;

    int row0 = tid >> 2;
    int kq = (tid & 3) * 4;
    const float* Ab0 = A + (size_t)(m0 + row0) * Dc + kq;
    const float* Ab1 = A + (size_t)(m0 + row0 + 64) * Dc + kq;
    const float* Bb0 = Wt + (size_t)(n0 + row0) * Dc + kq;
    const float* Bb1 = Wt + (size_t)(n0 + row0 + 64) * Dc + kq;

    // ldmatrix per-lane byte offsets (within a stage)
    int sub = lane >> 3;               // 0..3
    int r8 = lane & 7;
    uint32_t a_off[4];
#pragma unroll
    for (int mt = 0; mt < 4; mt++) {
        int arow = wm + mt * 16 + ((sub & 1) << 3) + r8;
        int acol = (sub & 2) << 1;     // 0 or 4
        a_off[mt] = (uint32_t)((arow * PADW + acol) * 4);
    }
    int l16 = lane & 15;
    uint32_t b_off[4];
#pragma unroll
    for (int nt = 0; nt < 4; nt++) {
        int brow = wn + nt * 8 + (l16 & 7);
        int bcol = (l16 >> 3) << 2;    // 0 or 4
        b_off[nt] = (uint32_t)((brow * PADW + bcol) * 4);
    }
    uint32_t As0 = smem_u32(As);
    uint32_t Bs0 = smem_u32(Bs);

    float acc[4][4][4];
#pragma unroll
    for (int i = 0; i < 4; i++)
#pragma unroll
        for (int j = 0; j < 4; j++)
#pragma unroll
            for (int e = 0; e < 4; e++) acc[i][j][e] = 0.f;

    const int nIter = Dc / 16;

#define FILL(st, koff)                                          \
    do {                                                        \
        float* as_ = As + (st) * STG;                           \
        float* bs_ = Bs + (st) * STG;                           \
        cpa16(as_ + row0 * PADW + kq, Ab0 + (koff));            \
        cpa16(as_ + (row0 + 64) * PADW + kq, Ab1 + (koff));     \
        cpa16(bs_ + row0 * PADW + kq, Bb0 + (koff));            \
        cpa16(bs_ + (row0 + 64) * PADW + kq, Bb1 + (koff));     \
    } while (0)

    FILL(0, 0); CP_COMMIT();
    FILL(1, 16); CP_COMMIT();
    FILL(2, 32); CP_COMMIT();

    for (int it = 0; it < nIter; it++) {
        CP_WAIT2();
        __syncthreads();

        if (it + 3 < nIter) FILL((it + 3) & 3, (it + 3) * 16);
        CP_COMMIT();

        uint32_t abase = As0 + (uint32_t)((it & 3) * STG * 4);
        uint32_t bbase = Bs0 + (uint32_t)((it & 3) * STG * 4);
#pragma unroll
        for (int ks = 0; ks < 16; ks += 8) {
            uint32_t ksb = (uint32_t)(ks * 4);
            uint32_t af[4][4], bf[4][2];
#pragma unroll
            for (int mt = 0; mt < 4; mt++)
                ldsm_x4(af[mt], abase + a_off[mt] + ksb);
#pragma unroll
            for (int nt = 0; nt < 4; nt++)
                ldsm_x2(bf[nt], bbase + b_off[nt] + ksb);
#pragma unroll
            for (int mt = 0; mt < 4; mt++)
#pragma unroll
                for (int nt = 0; nt < 4; nt++)
                    mma_tf32(acc[mt][nt][0], acc[mt][nt][1], acc[mt][nt][2], acc[mt][nt][3],
                             af[mt][0], af[mt][1], af[mt][2], af[mt][3],
                             bf[nt][0], bf[nt][1]);
        }
        __syncthreads();
    }
#undef FILL

#pragma unroll
    for (int mt = 0; mt < 4; mt++) {
#pragma unroll
        for (int nt = 0; nt < 4; nt++) {
            float* p = C + (size_t)(m0 + wm + mt * 16 + r) * Dc + n0 + wn + nt * 8 + 2 * c;
            float2 v0, v1;
            v0.x = alpha * acc[mt][nt][0];
            v0.y = alpha * acc[mt][nt][1];
            v1.x = alpha * acc[mt][nt][2];
            v1.y = alpha * acc[mt][nt][3];
            *(float2*)p = v0;
            *(float2*)(p + 8 * Dc) = v1;
        }
    }
}

// batched 4-way GEMM (q, k, v, q_g share the A matrix g_xn)
__global__ __launch_bounds__(256, 2) void tgemm4(const float* __restrict__ A,
                                                 float* __restrict__ o0,
                                                 float* __restrict__ o1,
                                                 float* __restrict__ o2,
                                                 float* __restrict__ o3) {
    __shared__ float As[NSTAGE * STG];
    __shared__ float Bs[NSTAGE * STG];
    const float* Wt = g_wr + ((size_t)blockIdx.z << 20);
    float* C;
    switch (blockIdx.z) {
        case 0: C = o0; break;
        case 1: C = o1; break;
        case 2: C = o2; break;
        default: C = o3; break;
    }
    gemm_body(A, Wt, C, 1.0f, blockIdx.x, blockIdx.y, As, Bs);
}

// batched 2-way GEMM for the tail: slot0 loc@wo (alpha .3), slot1 ret@wro
__global__ __launch_bounds__(256, 2) void tgemm2(const float* __restrict__ A0,
                                                 const float* __restrict__ A1,
                                                 float* __restrict__ o0,
                                                 float* __restrict__ o1) {
    __shared__ float As[NSTAGE * STG];
    __shared__ float Bs[NSTAGE * STG];
    const float* A = blockIdx.z ? A1 : A0;
    const float* Wt = g_wr + ((size_t)(4 + blockIdx.z) << 20);
    float* C = blockIdx.z ? o1 : o0;
    float alpha = blockIdx.z ? 1.0f : 0.3f;
    gemm_body(A, Wt, C, alpha, blockIdx.x, blockIdx.y, As, Bs);
}

// ---------------- gate v3: 8 rows/block, weights in registers per warp ------
__global__ __launch_bounds__(256) void gate_k(const float* __restrict__ wg,
                                              const float* __restrict__ bg) {
    __shared__ float hs[8][17];
    int tid = threadIdx.x;
    int lane = tid & 31;
    int w = tid >> 5;
    int r0 = blockIdx.x * 8;
#pragma unroll
    for (int hh = 0; hh < 2; hh++) {
        int h = w * 2 + hh;
        u64 wreg[16];
        const u64* wp = (const u64*)(wg + h * Dc) + lane;
#pragma unroll
        for (int i = 0; i < 16; i++) wreg[i] = wp[32 * i];
        float bias = bg[h];
        for (int r = 0; r < 8; r++) {
            const u64* xp = (const u64*)(g_xn + (size_t)(r0 + r) * Dc) + lane;
            u64 sp = 0ull;
#pragma unroll
            for (int i = 0; i < 16; i++) sp = fma2(xp[32 * i], wreg[i], sp);
            float lo, hi;
            unpack2(sp, lo, hi);
            float s = lo + hi;
#pragma unroll
            for (int o = 16; o > 0; o >>= 1)
                s += __shfl_xor_sync(0xffffffffu, s, o);
            if (lane == 0) hs[r][h] = 1.f / (1.f + __expf(-(s + bias)));
        }
    }
    __syncthreads();
    if (tid < 8) {
        float m = 0.f;
#pragma unroll
        for (int h = 0; h < 16; h++) m += hs[tid][h];
        g_gate[r0 + tid] = m * (1.f / 16.f);
    }
}

// ---------------- RoPE (in place; q and k in one launch) ----------------
__global__ __launch_bounds__(256) void rope_k(float* __restrict__ pq,
                                              float* __restrict__ pk) {
    float* p = blockIdx.y ? pk : pq;
    int gid = blockIdx.x * 256 + threadIdx.x;
    int row = gid >> 9;
    int rem = gid & 511;
    int h = rem >> 5;
    int i = rem & 31;
    int t = row & (Tc - 1);
    int base = row * Dc + h * 64 + i;
    float u1 = p[base];
    float u2 = p[base + 32];
    float fr = exp2f(-(float)i * 0.41524100184f);
    float ang = (float)t * fr;
    float cc, ss;
    __sincosf(ang, &ss, &cc);
    p[base] = u1 * cc - u2 * ss;
    p[base + 32] = u2 * cc + u1 * ss;
}

// ---------------- sliding-window attention: QK^T on tensor cores -----------
#define APAD 68
#define PPAD 65
#define ATTN_SMEM ((128 * APAD + 2 * 64 * APAD + 128 * PPAD) * 4)
__global__ __launch_bounds__(256) void attn_k() {
    extern __shared__ float sm[];
    float* qs = sm;                        // 128 x APAD (tf32)
    float* ks = qs + 128 * APAD;           // 64 x APAD (tf32)
    float* vs = ks + 64 * APAD;            // 64 x APAD (f32)
    float* ps = vs + 64 * APAD;            // 128 x PPAD (scores)
    int tid = threadIdx.x;
    int lane = tid & 31;
    int wid = tid >> 5;
    int q0 = blockIdx.x * 128;
    int h = blockIdx.y;
    int b = blockIdx.z;

    const float* qbase = g_q + (size_t)(b * Tc + q0) * Dc + h * 64;
#pragma unroll 4
    for (int it = 0; it < 32; it++) {
        int id = it * 256 + tid;
        int r = id >> 6, d = id & 63;
        qs[r * APAD + d] = tf32r(qbase[(size_t)r * Dc + d]);
    }

    int row = tid & 127;
    int half = tid >> 7;
    int tq = q0 + row;
    float m = -1e30f, l = 0.f;
    u64 accp[16];
#pragma unroll
    for (int i = 0; i < 16; i++) accp[i] = 0ull;

    int wm = wid * 16;
    int r4 = lane >> 2;
    int c4 = lane & 3;

    int s_start = q0 - Wc;
    if (s_start < 0) s_start = 0;
    __syncthreads();

    for (int s0 = s_start; s0 < q0 + 128; s0 += 64) {
        const float* kb = g_k + (size_t)(b * Tc + s0) * Dc + h * 64;
        const float* vb = g_v + (size_t)(b * Tc + s0) * Dc + h * 64;
#pragma unroll 4
        for (int it = 0; it < 16; it++) {
            int id = it * 256 + tid;
            int r = id >> 6, d = id & 63;
            ks[r * APAD + d] = tf32r(kb[(size_t)r * Dc + d]);
            vs[r * APAD + d] = vb[(size_t)r * Dc + d];
        }
        __syncthreads();

        float acc[8][4];
#pragma unroll
        for (int nt = 0; nt < 8; nt++)
#pragma unroll
            for (int e = 0; e < 4; e++) acc[nt][e] = 0.f;

#pragma unroll
        for (int ks8 = 0; ks8 < 64; ks8 += 8) {
            const uint32_t* ap = (const uint32_t*)qs + (wm + r4) * APAD + ks8 + c4;
            uint32_t a0 = ap[0];
            uint32_t a1 = ap[8 * APAD];
            uint32_t a2 = ap[4];
            uint32_t a3 = ap[8 * APAD + 4];
#pragma unroll
            for (int nt = 0; nt < 8; nt++) {
                const uint32_t* bp = (const uint32_t*)ks + (nt * 8 + r4) * APAD + ks8 + c4;
                mma_tf32(acc[nt][0], acc[nt][1], acc[nt][2], acc[nt][3],
                         a0, a1, a2, a3, bp[0], bp[4]);
            }
        }
#pragma unroll
        for (int nt = 0; nt < 8; nt++) {
            int col = nt * 8 + 2 * c4;
            float* p0 = ps + (wm + r4) * PPAD + col;
            float* p1 = ps + (wm + r4 + 8) * PPAD + col;
            p0[0] = acc[nt][0] * 0.125f;
            p0[1] = acc[nt][1] * 0.125f;
            p1[0] = acc[nt][2] * 0.125f;
            p1[1] = acc[nt][3] * 0.125f;
        }
        __syncthreads();

        const float* prow = ps + row * PPAD;
        int jhi = tq - s0;
        int jlo = jhi - Wc;
        float tmax = -1e30f;
        float sv[64];
#pragma unroll
        for (int j = 0; j < 64; j++) {
            float s = prow[j];
            if (j > jhi || j < jlo) s = -1e30f;
            sv[j] = s;
            tmax = fmaxf(tmax, s);
        }
        float mnew = fmaxf(m, tmax);
        float corr = __expf(m - mnew);
        l *= corr;
        u64 corrp = pack2(corr, corr);
#pragma unroll
        for (int i = 0; i < 16; i++) accp[i] = mul2(accp[i], corrp);
#pragma unroll
        for (int j = 0; j < 64; j++) {
            float p = (sv[j] > -1e29f) ? __expf(sv[j] - mnew) : 0.f;
            l += p;
            u64 pp = pack2(p, p);
            const u64* v2 = (const u64*)(vs + j * APAD + half * 32);
#pragma unroll
            for (int i = 0; i < 16; i++) accp[i] = fma2(pp, v2[i], accp[i]);
        }
        m = mnew;
        __syncthreads();
    }

    float inv = 1.f / l;
    float* ob = g_local + (size_t)(b * Tc + tq) * Dc + h * 64 + half * 32;
#pragma unroll
    for (int i = 0; i < 16; i++) {
        float lo, hi;
        unpack2(accp[i], lo, hi);
        ob[2 * i] = tf32r(lo * inv);
        ob[2 * i + 1] = tf32r(hi * inv);
    }
}

// ---------------- retrieval (output tf32-rounded) ----------------
__global__ __launch_bounds__(256) void retr_k(const float* __restrict__ state,
                                              const int* __restrict__ ids,
                                              const float* __restrict__ bank) {
    __shared__ float st[64 * 64];
    __shared__ float qs[4][64];
    int tc = blockIdx.x;
    int h = blockIdx.y;
    int b = blockIdx.z;
    int tid = threadIdx.x;
    const float* sb = state + (size_t)((b * Hc + h) * 64) * 64;
    for (int i = tid; i < 4096; i += 256) st[i] = sb[i];
    __syncthreads();
    int tloc = tid >> 6;
    int kk = tid & 63;
    for (int t0 = tc * 128; t0 < tc * 128 + 128; t0 += 4) {
        int t = t0 + tloc;
        int ii = ids[b * Tc + t] - CUE_C;
        float val;
        if (ii >= 0 && ii < BANK_C)
            val = bank[(size_t)(h * BANK_C + ii) * 64 + kk];
        else
            val = g_qg[(size_t)(b * Tc + t) * Dc + h * 64 + kk];
        qs[tloc][kk] = val;
        __syncthreads();
        float sum = 0.f;
#pragma unroll
        for (int k2 = 0; k2 < 64; k2++) sum += st[k2 * 64 + kk] * qs[tloc][k2];
        g_ret[(size_t)(b * Tc + t) * Dc + h * 64 + kk] = tf32r(sum);
        __syncthreads();
    }
}

// ---------------- final combine ----------------
__global__ __launch_bounds__(256) void combine_k(const float* __restrict__ x,
                                                 float* __restrict__ out) {
    int idx = blockIdx.x * 256 + threadIdx.x;
    int row = idx >> 8;
    float g = g_gate[row];
    float4 xv = ((const float4*)x)[idx];
    float4 lv = ((const float4*)g_localO)[idx];
    float4 rv = ((const float4*)g_ro)[idx];
    float4 o;
    o.x = xv.x + lv.x + g * rv.x;
    o.y = xv.y + lv.y + g * rv.y;
    o.z = xv.z + lv.z + g * rv.z;
    o.w = xv.w + lv.w + g * rv.w;
    ((float4*)out)[idx] = o;
}

// ---------------- launch ----------------
extern "C" void kernel_launch(void* const* d_in, const int* in_sizes, int n_in,
                              void* d_out, int out_size) {
    const float* x = (const float*)d_in[0];
    const float* gdn = (const float*)d_in[1];
    const int* ids = (const int*)d_in[2];
    const float* bank = (const float*)d_in[3];
    const float* normw = (const float*)d_in[4];
    const float* wq = (const float*)d_in[5];
    const float* wk = (const float*)d_in[6];
    const float* wv = (const float*)d_in[7];
    const float* wo = (const float*)d_in[8];
    const float* wgq = (const float*)d_in[9];
    const float* wro = (const float*)d_in[10];
    const float* wgate = (const float*)d_in[11];
    const float* bgate = (const float*)d_in[12];
    float* out = (float*)d_out;

    float *xn, *q, *k, *v, *qg, *loc, *locO, *ret, *ro;
    cudaGetSymbolAddress((void**)&xn, g_xn);
    cudaGetSymbolAddress((void**)&q, g_q);
    cudaGetSymbolAddress((void**)&k, g_k);
    cudaGetSymbolAddress((void**)&v, g_v);
    cudaGetSymbolAddress((void**)&qg, g_qg);
    cudaGetSymbolAddress((void**)&loc, g_local);
    cudaGetSymbolAddress((void**)&locO, g_localO);
    cudaGetSymbolAddress((void**)&ret, g_ret);
    cudaGetSymbolAddress((void**)&ro, g_ro);

    cudaFuncSetAttribute(attn_k, cudaFuncAttributeMaxDynamicSharedMemorySize,
                         ATTN_SMEM);

    // round weights: g_wr slots 0..5 = wq,wk,wv,wgq,wo,wro
    roundw_k<<<6144, 256>>>(wq, wk, wv, wgq, wo, wro);

    rmsnorm_k<<<MROWS, 256>>>(x, normw);

    dim3 gg4(Dc / 128, MROWS / 128, 4);  // 1024 blocks
    tgemm4<<<gg4, 256>>>(xn, q, k, v, qg);

    gate_k<<<MROWS / 8, 256>>>(wgate, bgate);

    rope_k<<<dim3((MROWS * Hc * 32) / 256, 2), 256>>>(q, k);

    retr_k<<<dim3(Tc / 128, Hc, Bc), 256>>>(gdn, ids, bank);

    attn_k<<<dim3(Tc / 128, Hc, Bc), 256, ATTN_SMEM>>>();

    dim3 gg2(Dc / 128, MROWS / 128, 2);  // 512 blocks
    tgemm2<<<gg2, 256>>>(loc, ret, locO, ro);

    combine_k<<<(MROWS * Dc / 4) / 256, 256>>>(x, out);
}